// round 10
// baseline (speedup 1.0000x reference)
#include <cuda_runtime.h>
#include <cuda_bf16.h>
#include <cuda_fp16.h>
#include <math.h>
#include <stdint.h>

#define B_   8
#define T_   512
#define D_   1024
#define H_   16
#define HD_  64
#define TA_  256
#define TB_  256
#define R_   128
#define TM_  384
#define NPAIR 65536
#define NCAP  2048

// ---------------- scratch (device globals) -----------------------------------
__device__ float              g_inv [B_*T_];
__device__ __align__(16) unsigned long long g_keys[B_*NPAIR];
__device__ unsigned long long g_cand[B_*NCAP];
__device__ int                g_hist[B_*4096];
__device__ int                g_cut [B_];
__device__ int                g_cnt [B_];
__device__ int                g_srcA[B_*TM_];
__device__ int                g_srcB[B_*TM_];
__device__ int                g_dst0[B_*TM_];
__device__ int                g_dst1[B_*TM_];
// fp16 operands for the attention GEMMs (A side hi/lo, B side hi only)
__device__ __align__(16) __half g_mhi [B_*TM_*D_];
__device__ __align__(16) __half g_mlo [B_*TM_*D_];
__device__ __align__(16) __half g_whi [4*D_*D_];
__device__ __align__(16) __half g_qhi [B_*H_*TM_*HD_];
__device__ __align__(16) __half g_qlo [B_*H_*TM_*HD_];
__device__ __align__(16) __half g_khi [B_*H_*TM_*HD_];
__device__ __align__(16) __half g_vhi [B_*H_*TM_*HD_];   // [bh][t][d]
__device__ __align__(16) __half g_ahi [B_*TM_*D_];
__device__ __align__(16) __half g_alo [B_*TM_*D_];
// packed even/odd token sets for similarity mma (bf16 3-term, exact-order path)
__device__ __align__(16) __nv_bfloat16 g_xahi[B_*TA_*D_];
__device__ __align__(16) __nv_bfloat16 g_xalo[B_*TA_*D_];
__device__ __align__(16) __nv_bfloat16 g_xbhi[B_*TB_*D_];
__device__ __align__(16) __nv_bfloat16 g_xblo[B_*TB_*D_];

// ---------------- helpers -----------------------------------------------------
__device__ __forceinline__ void bf16_split(float v, __nv_bfloat16& h, __nv_bfloat16& l)
{
    h = __float2bfloat16(v);
    l = __float2bfloat16(v - __bfloat162float(h));
}

__device__ __forceinline__ void fp16_split(float v, __half& h, __half& l)
{
    h = __float2half_rn(v);
    l = __float2half_rn(v - __half2float(h));
}

__device__ __forceinline__ uint4 ldm4(const void* p)
{
    uint4 r; unsigned a = (unsigned)__cvta_generic_to_shared(p);
    asm volatile("ldmatrix.sync.aligned.m8n8.x4.shared.b16 {%0,%1,%2,%3}, [%4];"
        : "=r"(r.x), "=r"(r.y), "=r"(r.z), "=r"(r.w) : "r"(a));
    return r;
}

__device__ __forceinline__ uint4 ldm4t(const void* p)
{
    uint4 r; unsigned a = (unsigned)__cvta_generic_to_shared(p);
    asm volatile("ldmatrix.sync.aligned.m8n8.x4.trans.shared.b16 {%0,%1,%2,%3}, [%4];"
        : "=r"(r.x), "=r"(r.y), "=r"(r.z), "=r"(r.w) : "r"(a));
    return r;
}

__device__ __forceinline__ void mma_bf(float* c, uint4 a, unsigned b0, unsigned b1)
{
    asm volatile("mma.sync.aligned.m16n8k16.row.col.f32.bf16.bf16.f32 "
        "{%0,%1,%2,%3},{%4,%5,%6,%7},{%8,%9},{%0,%1,%2,%3};"
        : "+f"(c[0]), "+f"(c[1]), "+f"(c[2]), "+f"(c[3])
        : "r"(a.x), "r"(a.y), "r"(a.z), "r"(a.w), "r"(b0), "r"(b1));
}

__device__ __forceinline__ void mma_h(float* c, uint4 a, unsigned b0, unsigned b1)
{
    asm volatile("mma.sync.aligned.m16n8k16.row.col.f32.f16.f16.f32 "
        "{%0,%1,%2,%3},{%4,%5,%6,%7},{%8,%9},{%0,%1,%2,%3};"
        : "+f"(c[0]), "+f"(c[1]), "+f"(c[2]), "+f"(c[3])
        : "r"(a.x), "r"(a.y), "r"(a.z), "r"(a.w), "r"(b0), "r"(b1));
}

__device__ __forceinline__ void cpa16(void* dst, const void* src)
{
    unsigned d = (unsigned)__cvta_generic_to_shared(dst);
    asm volatile("cp.async.ca.shared.global [%0], [%1], 16;" :: "r"(d), "l"(src));
}
__device__ __forceinline__ void cp_commit() { asm volatile("cp.async.commit_group;"); }
__device__ __forceinline__ void cp_wait1()  { asm volatile("cp.async.wait_group 1;"); }
__device__ __forceinline__ void cp_wait0()  { asm volatile("cp.async.wait_group 0;"); }

// ====== fp16 GEMM: C = (Ahi[+Alo]) · Bhi^T (ALO selects 2-term vs 1-term) =====
template<int BM, int BN, int WM, int WN, bool ALO>
struct MmaGemmH {
    static constexpr int MT  = BM / WM / 16;
    static constexpr int NTT = BN / WN / 8;
    static constexpr int BK  = 32;
    static constexpr int BKP = 40;
    static constexpr int AROWS = ALO ? 2 * BM : BM;
    static constexpr int STAGE = (AROWS + BN) * BKP;     // half elems per stage
    static constexpr int SMEM  = 2 * STAGE * 2;          // bytes

    __device__ static void prefetch(const __half* Ahi, const __half* Alo, int lda,
                                    const __half* Bhi, int ldb, int k0, __half* sbuf)
    {
        const int tid = threadIdx.x;
#pragma unroll
        for (int idx = tid; idx < BM * 4; idx += 256) {
            int m = idx >> 2, q = idx & 3;
            cpa16(sbuf + m * BKP + q * 8, Ahi + (size_t)m * lda + k0 + q * 8);
            if (ALO)
                cpa16(sbuf + BM * BKP + m * BKP + q * 8, Alo + (size_t)m * lda + k0 + q * 8);
        }
#pragma unroll
        for (int idx = tid; idx < BN * 4; idx += 256) {
            int n = idx >> 2, q = idx & 3;
            cpa16(sbuf + AROWS * BKP + n * BKP + q * 8, Bhi + (size_t)n * ldb + k0 + q * 8);
        }
    }

    __device__ static void run(const __half* Ahi, const __half* Alo, int lda,
                               const __half* Bhi, int ldb,
                               int K, float (&acc)[MT][NTT][4])
    {
        extern __shared__ unsigned char smem_raw[];
        __half* sm = (__half*)smem_raw;
        const int lane = threadIdx.x & 31;
        const int wid  = threadIdx.x >> 5;
        const int wrow = wid / WN, wcol = wid % WN;
#pragma unroll
        for (int i = 0; i < MT; i++)
#pragma unroll
            for (int j = 0; j < NTT; j++)
#pragma unroll
                for (int e = 0; e < 4; e++) acc[i][j][e] = 0.f;

        const int arow0 = wrow * (MT * 16) + (lane & 15);
        const int acolL = (lane >> 4) * 8;
        const int bg    = lane >> 3;
        const int brow0 = wcol * (NTT * 8) + ((bg >> 1) << 3) + (lane & 7);
        const int bcolL = (bg & 1) << 3;

        const int iters = K / BK;
        prefetch(Ahi, Alo, lda, Bhi, ldb, 0, sm);
        cp_commit();
        for (int it = 0; it < iters; it++) {
            if (it + 1 < iters) {
                prefetch(Ahi, Alo, lda, Bhi, ldb, (it + 1) * BK, sm + ((it + 1) & 1) * STAGE);
                cp_commit();
                cp_wait1();
            } else {
                cp_wait0();
            }
            __syncthreads();
            const __half* buf  = sm + (it & 1) * STAGE;
            const __half* sAhi = buf;
            const __half* sAlo = buf + BM * BKP;
            const __half* sBhi = buf + AROWS * BKP;
#pragma unroll
            for (int kk = 0; kk < 2; kk++) {
                uint4 ahi[MT], alo[MT];
#pragma unroll
                for (int i = 0; i < MT; i++) {
                    int off = (arow0 + i * 16) * BKP + kk * 16 + acolL;
                    ahi[i] = ldm4(sAhi + off);
                    if (ALO) alo[i] = ldm4(sAlo + off);
                }
#pragma unroll
                for (int jp = 0; jp < NTT / 2; jp++) {
                    int off = (brow0 + jp * 16) * BKP + kk * 16 + bcolL;
                    uint4 bhi = ldm4(sBhi + off);
#pragma unroll
                    for (int i = 0; i < MT; i++) {
                        mma_h(acc[i][2*jp],   ahi[i], bhi.x, bhi.y);
                        if (ALO) mma_h(acc[i][2*jp], alo[i], bhi.x, bhi.y);
                        mma_h(acc[i][2*jp+1], ahi[i], bhi.z, bhi.w);
                        if (ALO) mma_h(acc[i][2*jp+1], alo[i], bhi.z, bhi.w);
                    }
                }
            }
            __syncthreads();
        }
    }
};

// ====== bf16 3-term GEMM (similarity / exact-order path only) =================
template<int BM, int BN, int WM, int WN>
struct MmaGemmB {
    static constexpr int MT  = BM / WM / 16;
    static constexpr int NTT = BN / WN / 8;
    static constexpr int BK  = 32;
    static constexpr int BKP = 40;
    static constexpr int STAGE = (BM + BN) * 2 * BKP;
    static constexpr int SMEM  = 2 * STAGE * 2;

    __device__ static void prefetch(const __nv_bfloat16* Ahi, const __nv_bfloat16* Alo, int lda,
                                    const __nv_bfloat16* Bhi, const __nv_bfloat16* Blo, int ldb,
                                    int k0, __nv_bfloat16* sbuf)
    {
        const int tid = threadIdx.x;
#pragma unroll
        for (int idx = tid; idx < BM * 4; idx += 256) {
            int m = idx >> 2, q = idx & 3;
            cpa16(sbuf + m * BKP + q * 8,            Ahi + (size_t)m * lda + k0 + q * 8);
            cpa16(sbuf + BM * BKP + m * BKP + q * 8, Alo + (size_t)m * lda + k0 + q * 8);
        }
#pragma unroll
        for (int idx = tid; idx < BN * 4; idx += 256) {
            int n = idx >> 2, q = idx & 3;
            cpa16(sbuf + 2*BM*BKP + n * BKP + q * 8,          Bhi + (size_t)n * ldb + k0 + q * 8);
            cpa16(sbuf + 2*BM*BKP + BN*BKP + n * BKP + q * 8, Blo + (size_t)n * ldb + k0 + q * 8);
        }
    }

    __device__ static void run(const __nv_bfloat16* Ahi, const __nv_bfloat16* Alo, int lda,
                               const __nv_bfloat16* Bhi, const __nv_bfloat16* Blo, int ldb,
                               int K, float (&acc)[MT][NTT][4])
    {
        extern __shared__ unsigned char smem_raw[];
        __nv_bfloat16* sm = (__nv_bfloat16*)smem_raw;
        const int lane = threadIdx.x & 31;
        const int wid  = threadIdx.x >> 5;
        const int wrow = wid / WN, wcol = wid % WN;
#pragma unroll
        for (int i = 0; i < MT; i++)
#pragma unroll
            for (int j = 0; j < NTT; j++)
#pragma unroll
                for (int e = 0; e < 4; e++) acc[i][j][e] = 0.f;

        const int arow0 = wrow * (MT * 16) + (lane & 15);
        const int acolL = (lane >> 4) * 8;
        const int bg    = lane >> 3;
        const int brow0 = wcol * (NTT * 8) + ((bg >> 1) << 3) + (lane & 7);
        const int bcolL = (bg & 1) << 3;

        const int iters = K / BK;
        prefetch(Ahi, Alo, lda, Bhi, Blo, ldb, 0, sm);
        cp_commit();
        for (int it = 0; it < iters; it++) {
            if (it + 1 < iters) {
                prefetch(Ahi, Alo, lda, Bhi, Blo, ldb, (it + 1) * BK, sm + ((it + 1) & 1) * STAGE);
                cp_commit();
                cp_wait1();
            } else {
                cp_wait0();
            }
            __syncthreads();
            const __nv_bfloat16* buf  = sm + (it & 1) * STAGE;
            const __nv_bfloat16* sAhi = buf;
            const __nv_bfloat16* sAlo = buf + BM * BKP;
            const __nv_bfloat16* sBhi = buf + 2 * BM * BKP;
            const __nv_bfloat16* sBlo = buf + 2 * BM * BKP + BN * BKP;
#pragma unroll
            for (int kk = 0; kk < 2; kk++) {
                uint4 ahi[MT], alo[MT];
#pragma unroll
                for (int i = 0; i < MT; i++) {
                    int off = (arow0 + i * 16) * BKP + kk * 16 + acolL;
                    ahi[i] = ldm4(sAhi + off);
                    alo[i] = ldm4(sAlo + off);
                }
#pragma unroll
                for (int jp = 0; jp < NTT / 2; jp++) {
                    int off = (brow0 + jp * 16) * BKP + kk * 16 + bcolL;
                    uint4 bhi = ldm4(sBhi + off);
                    uint4 blo = ldm4(sBlo + off);
#pragma unroll
                    for (int i = 0; i < MT; i++) {
                        mma_bf(acc[i][2*jp],   ahi[i], bhi.x, bhi.y);
                        mma_bf(acc[i][2*jp],   ahi[i], blo.x, blo.y);
                        mma_bf(acc[i][2*jp],   alo[i], bhi.x, bhi.y);
                        mma_bf(acc[i][2*jp+1], ahi[i], bhi.z, bhi.w);
                        mma_bf(acc[i][2*jp+1], ahi[i], blo.z, blo.w);
                        mma_bf(acc[i][2*jp+1], alo[i], bhi.z, bhi.w);
                    }
                }
            }
            __syncthreads();
        }
    }
};

// ---------------- 1) fused prep: norms + even/odd split + hist zero ----------
__global__ void kprep(const float* __restrict__ x)
{
    int row = blockIdx.x;
    int b = row >> 9, t = row & 511;
    const float4* src = (const float4*)(x + (size_t)row * D_);
    int r2 = (b << 8) + (t >> 1);
    __nv_bfloat16* dh = ((t & 1) ? g_xbhi : g_xahi) + (size_t)r2 * D_;
    __nv_bfloat16* dl = ((t & 1) ? g_xblo : g_xalo) + (size_t)r2 * D_;
    int i = threadIdx.x;
    float4 v = src[i];
    float vv[4] = {v.x, v.y, v.z, v.w};
    __nv_bfloat16 hh[4], ll[4];
#pragma unroll
    for (int q = 0; q < 4; q++) bf16_split(vv[q], hh[q], ll[q]);
    __nv_bfloat162 t0, t1;
    t0.x = hh[0]; t0.y = hh[1]; t1.x = hh[2]; t1.y = hh[3];
    *(__nv_bfloat162*)(dh + i * 4)     = t0;
    *(__nv_bfloat162*)(dh + i * 4 + 2) = t1;
    t0.x = ll[0]; t0.y = ll[1]; t1.x = ll[2]; t1.y = ll[3];
    *(__nv_bfloat162*)(dl + i * 4)     = t0;
    *(__nv_bfloat162*)(dl + i * 4 + 2) = t1;

    float s = vv[0]*vv[0] + vv[1]*vv[1] + vv[2]*vv[2] + vv[3]*vv[3];
    __shared__ float red[8];
    for (int o = 16; o > 0; o >>= 1) s += __shfl_down_sync(0xffffffffu, s, o);
    if ((threadIdx.x & 31) == 0) red[threadIdx.x >> 5] = s;
    __syncthreads();
    if (threadIdx.x < 32) {
        float w = (threadIdx.x < 8) ? red[threadIdx.x] : 0.f;
        for (int o = 4; o > 0; o >>= 1) w += __shfl_down_sync(0xffffffffu, w, o);
        if (threadIdx.x == 0) g_inv[row] = 1.0f / fmaxf(sqrtf(w), 1e-12f);
    }
    if (row < 128) g_hist[row * 256 + threadIdx.x] = 0;
}

// ---------------- 2) similarity via bf16 3-term mma (64x64 tiles) ------------
__global__ void __launch_bounds__(256) ksim_mma()
{
    using G = MmaGemmB<64,64,2,4>;
    int b = blockIdx.z;
    int a0 = blockIdx.y * 64, c0 = blockIdx.x * 64;
    float acc[G::MT][G::NTT][4];
    G::run(g_xahi + ((size_t)(b * TA_ + a0)) * D_, g_xalo + ((size_t)(b * TA_ + a0)) * D_, D_,
           g_xbhi + ((size_t)(b * TB_ + c0)) * D_, g_xblo + ((size_t)(b * TB_ + c0)) * D_, D_,
           D_, acc);

    int lane = threadIdx.x & 31, wid = threadIdx.x >> 5;
    int wrow = wid / 4, wcol = wid % 4;
    int g = lane >> 2, t4 = lane & 3;
#pragma unroll
    for (int i = 0; i < G::MT; i++)
#pragma unroll
        for (int j = 0; j < G::NTT; j++)
#pragma unroll
            for (int e = 0; e < 4; e++) {
                int a = a0 + wrow * 32 + i * 16 + g + ((e >> 1) << 3);
                int c = c0 + wcol * 16 + j * 8 + 2 * t4 + (e & 1);
                float v = acc[i][j][e] * g_inv[b * T_ + 2 * a] * g_inv[b * T_ + 2 * c + 1];
                unsigned u = __float_as_uint(v);
                unsigned ord = u ^ ((u & 0x80000000u) ? 0xFFFFFFFFu : 0x80000000u);
                unsigned flat = (unsigned)(a * TB_ + c);
                g_keys[(size_t)b * NPAIR + flat] =
                    ((unsigned long long)ord << 32) | (unsigned)(~flat);
            }
}

// ---------------- 3) histogram path ------------------------------------------
__global__ void khist2()
{
    __shared__ int h[4096];
    int chunk = blockIdx.x, b = blockIdx.y, tid = threadIdx.x;
    for (int i = tid; i < 4096; i += 256) h[i] = 0;
    __syncthreads();
    const uint4* kv = (const uint4*)(g_keys + (size_t)b * NPAIR + chunk * 8192);
#pragma unroll 4
    for (int i = tid; i < 4096; i += 256) {
        uint4 v = kv[i];
        atomicAdd(&h[v.y >> 20], 1);
        atomicAdd(&h[v.w >> 20], 1);
    }
    __syncthreads();
    for (int i = tid; i < 4096; i += 256) {
        int v = h[i];
        if (v) atomicAdd(&g_hist[b * 4096 + i], v);
    }
}

__global__ void kcut()
{
    __shared__ int h[4096];
    __shared__ int strip[256];
    __shared__ int suffix[257];
    int b = blockIdx.x, tid = threadIdx.x;
    for (int i = tid; i < 4096; i += 256) h[i] = g_hist[b * 4096 + i];
    __syncthreads();
    int s = 0;
#pragma unroll
    for (int k = 0; k < 16; k++) s += h[tid * 16 + k];
    strip[tid] = s;
    __syncthreads();
    if (tid == 0) {
        int acc = 0;
        suffix[256] = 0;
        for (int i = 255; i >= 0; i--) { acc += strip[i]; suffix[i] = acc; }
    }
    __syncthreads();
    if (suffix[tid] >= 1024 && suffix[tid + 1] < 1024) {
        int c = suffix[tid + 1];
        int cut = tid * 16;
        for (int bkt = tid * 16 + 15; bkt >= tid * 16; bkt--) {
            c += h[bkt];
            if (c >= 1024) { cut = bkt; break; }
        }
        g_cut[b] = cut;
        g_cnt[b] = 0;
    }
}

// ---------------- 4) compact candidates above threshold ----------------------
__global__ void kcompact()
{
    int b = blockIdx.y;
    int base = blockIdx.x * 2048 + threadIdx.x;
    int cut = g_cut[b];
    const unsigned long long* keys = g_keys + (size_t)b * NPAIR;
#pragma unroll
    for (int r = 0; r < 8; r++) {
        int i = base + r * 256;
        unsigned long long k = keys[i];
        if ((int)(k >> 52) >= cut) {
            int pos = atomicAdd(&g_cnt[b], 1);
            if (pos < NCAP) g_cand[b * NCAP + pos] = k;
        }
    }
}

// ---------------- 5) sort candidates + exact greedy match --------------------
__device__ __forceinline__ void bitonic_sort_desc(unsigned long long* sk, int N, int tid, int nt)
{
    for (int k = 2; k <= N; k <<= 1) {
        for (int j = k >> 1; j > 0; j >>= 1) {
            for (int i = tid; i < N; i += nt) {
                int ixj = i ^ j;
                if (ixj > i) {
                    bool dir = ((i & k) == 0);
                    unsigned long long x0 = sk[i], x1 = sk[ixj];
                    if (dir ? (x0 < x1) : (x0 > x1)) { sk[i] = x1; sk[ixj] = x0; }
                }
            }
            __syncthreads();
        }
    }
}

__global__ void ksortgreedy()
{
    extern __shared__ unsigned char smem_raw[];
    unsigned long long* sk = (unsigned long long*)smem_raw;
    int b = blockIdx.x, tid = threadIdx.x;
    int cnt = g_cnt[b]; if (cnt > NCAP) cnt = NCAP;
    for (int i = tid; i < NCAP; i += 1024)
        sk[i] = (i < cnt) ? g_cand[b * NCAP + i] : 0ull;
    __syncthreads();
    bitonic_sort_desc(sk, NCAP, tid, 1024);
    if (tid == 0) {
        unsigned char ua[TA_], ub[TB_];
        int partner[TA_];
        for (int i = 0; i < TA_; i++) { ua[i] = 0; partner[i] = -1; }
        for (int i = 0; i < TB_; i++) ub[i] = 0;
        int m = 0;
        for (int i = 0; i < cnt && m < R_; i++) {
            unsigned flat = ~(unsigned)sk[i];
            int a = (int)(flat >> 8), c = (int)(flat & 255u);
            if (!ua[a] && !ub[c]) { ua[a] = 1; ub[c] = 1; partner[a] = c; m++; }
        }
        for (int i = 0; i < TA_; i++) {
            int p = partner[i];
            g_srcA[b * TM_ + i] = 2 * i;
            g_srcB[b * TM_ + i] = (p >= 0) ? (2 * p + 1) : -1;
            g_dst0[b * TM_ + i] = 2 * i;
            g_dst1[b * TM_ + i] = (p >= 0) ? (2 * p + 1) : -1;
        }
        int j = 0;
        for (int c = 0; c < TB_; c++) if (!ub[c]) {
            int mm = TA_ + j;
            g_srcA[b * TM_ + mm] = 2 * c + 1;
            g_srcB[b * TM_ + mm] = -1;
            g_dst0[b * TM_ + mm] = 2 * c + 1;
            g_dst1[b * TM_ + mm] = -1;
            j++;
        }
    }
}

// ---------------- 6) merged sequence -> fp16 hi/lo ---------------------------
__global__ void kmerge(const float* __restrict__ x)
{
    int bm = blockIdx.x;
    int b = bm / TM_;
    int sA = g_srcA[bm], sB = g_srcB[bm];
    const float4* pa = (const float4*)(x + ((size_t)(b * T_ + sA)) * D_);
    const float4* pb = (sB >= 0) ? (const float4*)(x + ((size_t)(b * T_ + sB)) * D_) : nullptr;
    __half* mhi = g_mhi + (size_t)bm * D_;
    __half* mlo = g_mlo + (size_t)bm * D_;
    for (int i = threadIdx.x; i < D_ / 4; i += blockDim.x) {
        float4 a = pa[i];
        float v[4] = {a.x, a.y, a.z, a.w};
        if (pb) {
            float4 c = pb[i];
            v[0] = 0.5f * (v[0] + c.x); v[1] = 0.5f * (v[1] + c.y);
            v[2] = 0.5f * (v[2] + c.z); v[3] = 0.5f * (v[3] + c.w);
        }
        __half hh[4], ll[4];
#pragma unroll
        for (int q = 0; q < 4; q++) fp16_split(v[q], hh[q], ll[q]);
        __half2 t0, t1;
        t0.x = hh[0]; t0.y = hh[1]; t1.x = hh[2]; t1.y = hh[3];
        *(__half2*)(mhi + i * 4)     = t0;
        *(__half2*)(mhi + i * 4 + 2) = t1;
        t0.x = ll[0]; t0.y = ll[1]; t1.x = ll[2]; t1.y = ll[3];
        *(__half2*)(mlo + i * 4)     = t0;
        *(__half2*)(mlo + i * 4 + 2) = t1;
    }
}

// ---------------- 7) weight conversion (fp16 hi only) ------------------------
__global__ void kconvw(const float* __restrict__ Wq, const float* __restrict__ Wk,
                       const float* __restrict__ Wv, const float* __restrict__ Wo)
{
    int mat = blockIdx.y;
    const float* W = (mat == 0) ? Wq : (mat == 1) ? Wk : (mat == 2) ? Wv : Wo;
    size_t base = (size_t)mat * D_ * D_;
    int idx = blockIdx.x * 256 + threadIdx.x;
    float4 v = *(const float4*)(W + (size_t)idx * 4);
    __half2 t0, t1;
    t0.x = __float2half_rn(v.x); t0.y = __float2half_rn(v.y);
    t1.x = __float2half_rn(v.z); t1.y = __float2half_rn(v.w);
    *(__half2*)(g_whi + base + (size_t)idx * 4)     = t0;
    *(__half2*)(g_whi + base + (size_t)idx * 4 + 2) = t1;
}

// ---------------- 8a) Q projection (fp16 2-term) -----------------------------
__global__ void __launch_bounds__(256) kq()
{
    using G = MmaGemmH<128,128,4,2,true>;
    int m0 = blockIdx.y * 128, n0 = blockIdx.x * 128;
    const __half* Bhi = g_whi + (size_t)n0 * D_;
    float acc[G::MT][G::NTT][4];
    G::run(g_mhi + (size_t)m0 * D_, g_mlo + (size_t)m0 * D_, D_, Bhi, D_, D_, acc);

    int lane = threadIdx.x & 31, wid = threadIdx.x >> 5;
    int wrow = wid / 2, wcol = wid % 2;
    int g = lane >> 2, t4 = lane & 3;
#pragma unroll
    for (int i = 0; i < G::MT; i++)
#pragma unroll
        for (int rr = 0; rr < 2; rr++) {
            int m = m0 + wrow * 32 + i * 16 + g + rr * 8;
            int b = m / TM_, t = m % TM_;
#pragma unroll
            for (int j = 0; j < G::NTT; j++) {
                int n = n0 + wcol * 64 + j * 8 + 2 * t4;
                int h = n >> 6, d = n & 63;
                size_t base = (((size_t)(b * H_ + h)) * TM_ + t) * HD_ + d;
                __half h0, l0, h1, l1;
                fp16_split(acc[i][j][rr * 2] * 0.125f, h0, l0);
                fp16_split(acc[i][j][rr * 2 + 1] * 0.125f, h1, l1);
                __half2 th, tl;
                th.x = h0; th.y = h1; *(__half2*)(g_qhi + base) = th;
                tl.x = l0; tl.y = l1; *(__half2*)(g_qlo + base) = tl;
            }
        }
}

// ---------------- 8b) K/V projection (fp16 1-term; output quantized anyway) --
__global__ void __launch_bounds__(256) kkv()
{
    using G = MmaGemmH<128,128,4,2,false>;
    int z = blockIdx.z + 1;                    // 1 = K, 2 = V
    int m0 = blockIdx.y * 128, n0 = blockIdx.x * 128;
    const __half* Bhi = g_whi + (size_t)z * D_ * D_ + (size_t)n0 * D_;
    float acc[G::MT][G::NTT][4];
    G::run(g_mhi + (size_t)m0 * D_, nullptr, D_, Bhi, D_, D_, acc);

    int lane = threadIdx.x & 31, wid = threadIdx.x >> 5;
    int wrow = wid / 2, wcol = wid % 2;
    int g = lane >> 2, t4 = lane & 3;
    __half* Dst = (z == 1) ? g_khi : g_vhi;
#pragma unroll
    for (int i = 0; i < G::MT; i++)
#pragma unroll
        for (int rr = 0; rr < 2; rr++) {
            int m = m0 + wrow * 32 + i * 16 + g + rr * 8;
            int b = m / TM_, t = m % TM_;
#pragma unroll
            for (int j = 0; j < G::NTT; j++) {
                int n = n0 + wcol * 64 + j * 8 + 2 * t4;
                int h = n >> 6, d = n & 63;
                size_t base = (((size_t)(b * H_ + h)) * TM_ + t) * HD_ + d;
                __half2 th;
                th.x = __float2half_rn(acc[i][j][rr * 2]);
                th.y = __float2half_rn(acc[i][j][rr * 2 + 1]);
                *(__half2*)(Dst + base) = th;
            }
        }
}

// ---------------- 9) fused attention (fp16; P hi-only in PV) -----------------
#define ATTN_SMEM 98304
__global__ void __launch_bounds__(256) kattn()
{
    extern __shared__ unsigned char smem_raw[];
    __half* sm = (__half*)smem_raw;
    float* smax0 = (float*)(smem_raw + 97280);
    float* smax1 = smax0 + 64;
    float* ssum0 = smax0 + 128;
    float* ssum1 = smax0 + 192;

    const int bh = blockIdx.y;
    const int m0 = blockIdx.x * 64;
    const int tid = threadIdx.x, lane = tid & 31, wid = tid >> 5;
    const int wrow = wid >> 1, wcol = wid & 1;
    const int g = lane >> 2, t4 = lane & 3;

    __half* sQhi = sm;
    __half* sQlo = sm + 4608;
    __half* sKhi = sm + 9216;

    {
        const __half* qh = g_qhi + ((size_t)bh * TM_ + m0) * HD_;
        const __half* ql = g_qlo + ((size_t)bh * TM_ + m0) * HD_;
        for (int idx = tid; idx < 64 * 8; idx += 256) {
            int r = idx >> 3, q = idx & 7;
            *(uint4*)(sQhi + r * 72 + q * 8) = *(const uint4*)(qh + r * HD_ + q * 8);
            *(uint4*)(sQlo + r * 72 + q * 8) = *(const uint4*)(ql + r * HD_ + q * 8);
        }
        const __half* kh = g_khi + (size_t)bh * TM_ * HD_;
        for (int idx = tid; idx < 384 * 8; idx += 256) {
            int r = idx >> 3, q = idx & 7;
            *(uint4*)(sKhi + r * 72 + q * 8) = *(const uint4*)(kh + r * HD_ + q * 8);
        }
    }
    __syncthreads();

    float acc[24][4];
#pragma unroll
    for (int j = 0; j < 24; j++)
#pragma unroll
        for (int e = 0; e < 4; e++) acc[j][e] = 0.f;

    const int arow  = wrow * 16 + (lane & 15);
    const int acolL = (lane >> 4) * 8;
    const int bg    = lane >> 3;
    const int brow0 = wcol * 192 + ((bg >> 1) << 3) + (lane & 7);
    const int bcolL = (bg & 1) << 3;

#pragma unroll
    for (int kk = 0; kk < 4; kk++) {
        uint4 ahi = ldm4(sQhi + arow * 72 + kk * 16 + acolL);
        uint4 alo = ldm4(sQlo + arow * 72 + kk * 16 + acolL);
#pragma unroll
        for (int jp = 0; jp < 12; jp++) {
            int off = (brow0 + jp * 16) * 72 + kk * 16 + bcolL;
            uint4 bhi = ldm4(sKhi + off);
            mma_h(acc[2*jp],   ahi, bhi.x, bhi.y);
            mma_h(acc[2*jp],   alo, bhi.x, bhi.y);
            mma_h(acc[2*jp+1], ahi, bhi.z, bhi.w);
            mma_h(acc[2*jp+1], alo, bhi.z, bhi.w);
        }
    }

    const int r0 = wrow * 16 + g, r1 = r0 + 8;
    float mx0 = -1e30f, mx1 = -1e30f;
#pragma unroll
    for (int j = 0; j < 24; j++) {
        mx0 = fmaxf(mx0, fmaxf(acc[j][0], acc[j][1]));
        mx1 = fmaxf(mx1, fmaxf(acc[j][2], acc[j][3]));
    }
    mx0 = fmaxf(mx0, __shfl_xor_sync(0xffffffffu, mx0, 1));
    mx0 = fmaxf(mx0, __shfl_xor_sync(0xffffffffu, mx0, 2));
    mx1 = fmaxf(mx1, __shfl_xor_sync(0xffffffffu, mx1, 1));
    mx1 = fmaxf(mx1, __shfl_xor_sync(0xffffffffu, mx1, 2));
    if (t4 == 0) {
        (wcol ? smax1 : smax0)[r0] = mx0;
        (wcol ? smax1 : smax0)[r1] = mx1;
    }
    __syncthreads();
    float M0 = fmaxf(smax0[r0], smax1[r0]);
    float M1 = fmaxf(smax0[r1], smax1[r1]);
    float s0 = 0.f, s1 = 0.f;
#pragma unroll
    for (int j = 0; j < 24; j++) {
        acc[j][0] = expf(acc[j][0] - M0); s0 += acc[j][0];
        acc[j][1] = expf(acc[j][1] - M0); s0 += acc[j][1];
        acc[j][2] = expf(acc[j][2] - M1); s1 += acc[j][2];
        acc[j][3] = expf(acc[j][3] - M1); s1 += acc[j][3];
    }
    s0 += __shfl_xor_sync(0xffffffffu, s0, 1); s0 += __shfl_xor_sync(0xffffffffu, s0, 2);
    s1 += __shfl_xor_sync(0xffffffffu, s1, 1); s1 += __shfl_xor_sync(0xffffffffu, s1, 2);
    if (t4 == 0) {
        (wcol ? ssum1 : ssum0)[r0] = s0;
        (wcol ? ssum1 : ssum0)[r1] = s1;
    }
    __syncthreads();

    {
        __half* sPhi = sm + 9216 + wcol * 12800;
#pragma unroll
        for (int j = 0; j < 24; j++) {
            int col = j * 8 + 2 * t4;
            __half2 th;
            th.x = __float2half_rn(acc[j][0]);
            th.y = __float2half_rn(acc[j][1]);
            *(__half2*)(sPhi + r0 * 200 + col) = th;
            th.x = __float2half_rn(acc[j][2]);
            th.y = __float2half_rn(acc[j][3]);
            *(__half2*)(sPhi + r1 * 200 + col) = th;
        }
    }
    __syncthreads();

    float acc2[4][4];
#pragma unroll
    for (int j = 0; j < 4; j++)
#pragma unroll
        for (int e = 0; e < 4; e++) acc2[j][e] = 0.f;

    __half* sVhi = sm + 34816;
    const int arow2 = wrow * 16 + (lane & 15);
    const int vrowL = ((bg & 1) << 3) + (lane & 7);
    const int vcolL = (bg >> 1) << 3;

    for (int c = 0; c < 2; c++) {
        if (c) __syncthreads();
        const __half* vh = g_vhi + ((size_t)bh * TM_ + c * 192) * HD_;
        for (int idx = tid; idx < 192 * 8; idx += 256) {
            int r = idx >> 3, q = idx & 7;
            *(uint4*)(sVhi + r * 72 + q * 8) = *(const uint4*)(vh + r * HD_ + q * 8);
        }
        __syncthreads();
        const __half* cPhi = sm + 9216 + c * 12800;
#pragma unroll
        for (int kk = 0; kk < 12; kk++) {
            uint4 phi = ldm4(cPhi + arow2 * 200 + kk * 16 + acolL);
#pragma unroll
            for (int jp = 0; jp < 2; jp++) {
                int off = (kk * 16 + vrowL) * 72 + wcol * 32 + jp * 16 + vcolL;
                uint4 vhi = ldm4t(sVhi + off);
                mma_h(acc2[2*jp],   phi, vhi.x, vhi.y);
                mma_h(acc2[2*jp+1], phi, vhi.z, vhi.w);
            }
        }
    }

    const int b = bh >> 4, hh = bh & 15;
    const float inv0 = 1.0f / (ssum0[r0] + ssum1[r0]);
    const float inv1 = 1.0f / (ssum0[r1] + ssum1[r1]);
#pragma unroll
    for (int j = 0; j < 4; j++) {
        int col = (wid & 1) * 32 + j * 8 + 2 * t4;
        int t  = m0 + r0;
        size_t o0 = ((size_t)(b * TM_ + t)) * D_ + hh * HD_ + col;
        size_t o1 = ((size_t)(b * TM_ + t + 8)) * D_ + hh * HD_ + col;
        __half h0, l0, h1, l1;
        __half2 th, tl;
        fp16_split(acc2[j][0] * inv0, h0, l0); fp16_split(acc2[j][1] * inv0, h1, l1);
        th.x = h0; th.y = h1; *(__half2*)(g_ahi + o0) = th;
        tl.x = l0; tl.y = l1; *(__half2*)(g_alo + o0) = tl;
        fp16_split(acc2[j][2] * inv1, h0, l0); fp16_split(acc2[j][3] * inv1, h1, l1);
        th.x = h0; th.y = h1; *(__half2*)(g_ahi + o1) = th;
        tl.x = l0; tl.y = l1; *(__half2*)(g_alo + o1) = tl;
    }
}

// ---------------- 10) output projection + fused unmerge scatter --------------
__global__ void __launch_bounds__(256) kout(float* __restrict__ out)
{
    using G = MmaGemmH<128,128,4,2,true>;
    int m0 = blockIdx.y * 128, n0 = blockIdx.x * 128;
    const __half* Bhi = g_whi + (size_t)3 * D_ * D_ + (size_t)n0 * D_;
    float acc[G::MT][G::NTT][4];
    G::run(g_ahi + (size_t)m0 * D_, g_alo + (size_t)m0 * D_, D_, Bhi, D_, D_, acc);

    int lane = threadIdx.x & 31, wid = threadIdx.x >> 5;
    int wrow = wid / 2, wcol = wid % 2;
    int g = lane >> 2, t4 = lane & 3;
#pragma unroll
    for (int i = 0; i < G::MT; i++) {
#pragma unroll
        for (int rr = 0; rr < 2; rr++) {
            int m = m0 + wrow * 32 + i * 16 + g + rr * 8;
            int b = m / TM_, mm = m % TM_;
            int d0 = g_dst0[b * TM_ + mm];
            int d1 = g_dst1[b * TM_ + mm];
#pragma unroll
            for (int j = 0; j < G::NTT; j++) {
                int n = n0 + wcol * 64 + j * 8 + 2 * t4;
                float2 v = make_float2(acc[i][j][rr * 2], acc[i][j][rr * 2 + 1]);
                *(float2*)&out[((size_t)(b * T_ + d0)) * D_ + n] = v;
                if (d1 >= 0) *(float2*)&out[((size_t)(b * T_ + d1)) * D_ + n] = v;
            }
        }
    }
}

// ---------------- launcher ----------------------------------------------------
extern "C" void kernel_launch(void* const* d_in, const int* in_sizes, int n_in,
                              void* d_out, int out_size)
{
    const float* x  = (const float*)d_in[0];
    const float* Wq = (const float*)d_in[1];
    const float* Wk = (const float*)d_in[2];
    const float* Wv = (const float*)d_in[3];
    const float* Wo = (const float*)d_in[4];
    float* out = (float*)d_out;

    const int smem_h2 = MmaGemmH<128,128,4,2,true>::SMEM;   // 61440
    const int smem_h1 = MmaGemmH<128,128,4,2,false>::SMEM;  // 40960
    const int smem_b  = MmaGemmB<64,64,2,4>::SMEM;          // 40960

    cudaFuncSetAttribute(kq,       cudaFuncAttributeMaxDynamicSharedMemorySize, smem_h2);
    cudaFuncSetAttribute(kkv,      cudaFuncAttributeMaxDynamicSharedMemorySize, smem_h1);
    cudaFuncSetAttribute(kout,     cudaFuncAttributeMaxDynamicSharedMemorySize, smem_h2);
    cudaFuncSetAttribute(ksim_mma, cudaFuncAttributeMaxDynamicSharedMemorySize, smem_b);
    cudaFuncSetAttribute(kattn,    cudaFuncAttributeMaxDynamicSharedMemorySize, ATTN_SMEM);

    kconvw<<<dim3(1024, 4), 256>>>(Wq, Wk, Wv, Wo);
    kprep<<<B_ * T_, 256>>>(x);
    ksim_mma<<<dim3(4, 4, B_), 256, smem_b>>>();
    khist2<<<dim3(8, B_), 256>>>();
    kcut<<<B_, 256>>>();
    kcompact<<<dim3(32, B_), 256>>>();
    ksortgreedy<<<B_, 1024, NCAP * 8>>>();
    kmerge<<<B_ * TM_, 256>>>(x);
    kq<<<dim3(8, 24), 256, smem_h2>>>();
    kkv<<<dim3(8, 24, 2), 256, smem_h1>>>();
    kattn<<<dim3(6, B_ * H_), 256, ATTN_SMEM>>>();
    kout<<<dim3(8, 24), 256, smem_h2>>>(out);
}

// round 11
// speedup vs baseline: 1.1485x; 1.1485x over previous
#include <cuda_runtime.h>
#include <cuda_bf16.h>
#include <cuda_fp16.h>
#include <math.h>
#include <stdint.h>

#define B_   8
#define T_   512
#define D_   1024
#define H_   16
#define HD_  64
#define TA_  256
#define TB_  256
#define R_   128
#define TM_  384
#define NPAIR 65536
#define NCAP  2048

// ---------------- scratch (device globals) -----------------------------------
__device__ float              g_inv [B_*T_];
__device__ __align__(16) unsigned long long g_keys[B_*NPAIR];
__device__ int                g_hist[B_*4096];
__device__ int                g_done[B_];
__device__ int                g_cut [B_];
__device__ int                g_srcA[B_*TM_];
__device__ int                g_srcB[B_*TM_];
__device__ int                g_dst0[B_*TM_];
__device__ int                g_dst1[B_*TM_];
// fp16 operands (A side hi/lo, B side hi only)
__device__ __align__(16) __half g_mhi [B_*TM_*D_];
__device__ __align__(16) __half g_mlo [B_*TM_*D_];
__device__ __align__(16) __half g_whi [4*D_*D_];
__device__ __align__(16) __half g_qhi [B_*H_*TM_*HD_];
__device__ __align__(16) __half g_qlo [B_*H_*TM_*HD_];
__device__ __align__(16) __half g_khi [B_*H_*TM_*HD_];
__device__ __align__(16) __half g_vhi [B_*H_*TM_*HD_];
__device__ __align__(16) __half g_ahi [B_*TM_*D_];
__device__ __align__(16) __half g_alo [B_*TM_*D_];
// packed even/odd token sets for similarity mma (bf16 3-term, exact-order path)
__device__ __align__(16) __nv_bfloat16 g_xahi[B_*TA_*D_];
__device__ __align__(16) __nv_bfloat16 g_xalo[B_*TA_*D_];
__device__ __align__(16) __nv_bfloat16 g_xbhi[B_*TB_*D_];
__device__ __align__(16) __nv_bfloat16 g_xblo[B_*TB_*D_];

// ---------------- helpers -----------------------------------------------------
__device__ __forceinline__ void bf16_split(float v, __nv_bfloat16& h, __nv_bfloat16& l)
{
    h = __float2bfloat16(v);
    l = __float2bfloat16(v - __bfloat162float(h));
}

__device__ __forceinline__ void fp16_split(float v, __half& h, __half& l)
{
    h = __float2half_rn(v);
    l = __float2half_rn(v - __half2float(h));
}

__device__ __forceinline__ uint4 ldm4(const void* p)
{
    uint4 r; unsigned a = (unsigned)__cvta_generic_to_shared(p);
    asm volatile("ldmatrix.sync.aligned.m8n8.x4.shared.b16 {%0,%1,%2,%3}, [%4];"
        : "=r"(r.x), "=r"(r.y), "=r"(r.z), "=r"(r.w) : "r"(a));
    return r;
}

__device__ __forceinline__ uint4 ldm4t(const void* p)
{
    uint4 r; unsigned a = (unsigned)__cvta_generic_to_shared(p);
    asm volatile("ldmatrix.sync.aligned.m8n8.x4.trans.shared.b16 {%0,%1,%2,%3}, [%4];"
        : "=r"(r.x), "=r"(r.y), "=r"(r.z), "=r"(r.w) : "r"(a));
    return r;
}

__device__ __forceinline__ void mma_bf(float* c, uint4 a, unsigned b0, unsigned b1)
{
    asm volatile("mma.sync.aligned.m16n8k16.row.col.f32.bf16.bf16.f32 "
        "{%0,%1,%2,%3},{%4,%5,%6,%7},{%8,%9},{%0,%1,%2,%3};"
        : "+f"(c[0]), "+f"(c[1]), "+f"(c[2]), "+f"(c[3])
        : "r"(a.x), "r"(a.y), "r"(a.z), "r"(a.w), "r"(b0), "r"(b1));
}

__device__ __forceinline__ void mma_h(float* c, uint4 a, unsigned b0, unsigned b1)
{
    asm volatile("mma.sync.aligned.m16n8k16.row.col.f32.f16.f16.f32 "
        "{%0,%1,%2,%3},{%4,%5,%6,%7},{%8,%9},{%0,%1,%2,%3};"
        : "+f"(c[0]), "+f"(c[1]), "+f"(c[2]), "+f"(c[3])
        : "r"(a.x), "r"(a.y), "r"(a.z), "r"(a.w), "r"(b0), "r"(b1));
}

__device__ __forceinline__ void cpa16(void* dst, const void* src)
{
    unsigned d = (unsigned)__cvta_generic_to_shared(dst);
    asm volatile("cp.async.ca.shared.global [%0], [%1], 16;" :: "r"(d), "l"(src));
}
__device__ __forceinline__ void cp_commit() { asm volatile("cp.async.commit_group;"); }
__device__ __forceinline__ void cp_wait1()  { asm volatile("cp.async.wait_group 1;"); }
__device__ __forceinline__ void cp_wait0()  { asm volatile("cp.async.wait_group 0;"); }

// ====== fp16 GEMM, BK=64: C = (Ahi[+Alo]) · Bhi^T =============================
template<int BM, int BN, int WM, int WN, bool ALO>
struct MmaGemmH {
    static constexpr int MT  = BM / WM / 16;
    static constexpr int NTT = BN / WN / 8;
    static constexpr int BK  = 64;
    static constexpr int BKP = 72;
    static constexpr int AROWS = ALO ? 2 * BM : BM;
    static constexpr int STAGE = (AROWS + BN) * BKP;     // half elems per stage
    static constexpr int SMEM  = 2 * STAGE * 2;          // bytes

    __device__ static void prefetch(const __half* Ahi, const __half* Alo, int lda,
                                    const __half* Bhi, int ldb, int k0, __half* sbuf)
    {
        const int tid = threadIdx.x;
#pragma unroll
        for (int idx = tid; idx < BM * 8; idx += 256) {
            int m = idx >> 3, q = idx & 7;
            cpa16(sbuf + m * BKP + q * 8, Ahi + (size_t)m * lda + k0 + q * 8);
            if (ALO)
                cpa16(sbuf + BM * BKP + m * BKP + q * 8, Alo + (size_t)m * lda + k0 + q * 8);
        }
#pragma unroll
        for (int idx = tid; idx < BN * 8; idx += 256) {
            int n = idx >> 3, q = idx & 7;
            cpa16(sbuf + AROWS * BKP + n * BKP + q * 8, Bhi + (size_t)n * ldb + k0 + q * 8);
        }
    }

    __device__ static void run(const __half* Ahi, const __half* Alo, int lda,
                               const __half* Bhi, int ldb,
                               int K, float (&acc)[MT][NTT][4])
    {
        extern __shared__ unsigned char smem_raw[];
        __half* sm = (__half*)smem_raw;
        const int lane = threadIdx.x & 31;
        const int wid  = threadIdx.x >> 5;
        const int wrow = wid / WN, wcol = wid % WN;
#pragma unroll
        for (int i = 0; i < MT; i++)
#pragma unroll
            for (int j = 0; j < NTT; j++)
#pragma unroll
                for (int e = 0; e < 4; e++) acc[i][j][e] = 0.f;

        const int arow0 = wrow * (MT * 16) + (lane & 15);
        const int acolL = (lane >> 4) * 8;
        const int bg    = lane >> 3;
        const int brow0 = wcol * (NTT * 8) + ((bg >> 1) << 3) + (lane & 7);
        const int bcolL = (bg & 1) << 3;

        const int iters = K / BK;
        prefetch(Ahi, Alo, lda, Bhi, ldb, 0, sm);
        cp_commit();
        for (int it = 0; it < iters; it++) {
            if (it + 1 < iters) {
                prefetch(Ahi, Alo, lda, Bhi, ldb, (it + 1) * BK, sm + ((it + 1) & 1) * STAGE);
                cp_commit();
                cp_wait1();
            } else {
                cp_wait0();
            }
            __syncthreads();
            const __half* buf  = sm + (it & 1) * STAGE;
            const __half* sAhi = buf;
            const __half* sAlo = buf + BM * BKP;
            const __half* sBhi = buf + AROWS * BKP;
#pragma unroll
            for (int kk = 0; kk < 4; kk++) {
                uint4 ahi[MT], alo[MT];
#pragma unroll
                for (int i = 0; i < MT; i++) {
                    int off = (arow0 + i * 16) * BKP + kk * 16 + acolL;
                    ahi[i] = ldm4(sAhi + off);
                    if (ALO) alo[i] = ldm4(sAlo + off);
                }
#pragma unroll
                for (int jp = 0; jp < NTT / 2; jp++) {
                    int off = (brow0 + jp * 16) * BKP + kk * 16 + bcolL;
                    uint4 bhi = ldm4(sBhi + off);
#pragma unroll
                    for (int i = 0; i < MT; i++) {
                        mma_h(acc[i][2*jp],   ahi[i], bhi.x, bhi.y);
                        if (ALO) mma_h(acc[i][2*jp], alo[i], bhi.x, bhi.y);
                        mma_h(acc[i][2*jp+1], ahi[i], bhi.z, bhi.w);
                        if (ALO) mma_h(acc[i][2*jp+1], alo[i], bhi.z, bhi.w);
                    }
                }
            }
            __syncthreads();
        }
    }
};

// ====== bf16 3-term GEMM (similarity / exact-order path only) =================
template<int BM, int BN, int WM, int WN>
struct MmaGemmB {
    static constexpr int MT  = BM / WM / 16;
    static constexpr int NTT = BN / WN / 8;
    static constexpr int BK  = 32;
    static constexpr int BKP = 40;
    static constexpr int STAGE = (BM + BN) * 2 * BKP;
    static constexpr int SMEM  = 2 * STAGE * 2;

    __device__ static void prefetch(const __nv_bfloat16* Ahi, const __nv_bfloat16* Alo, int lda,
                                    const __nv_bfloat16* Bhi, const __nv_bfloat16* Blo, int ldb,
                                    int k0, __nv_bfloat16* sbuf)
    {
        const int tid = threadIdx.x;
#pragma unroll
        for (int idx = tid; idx < BM * 4; idx += 256) {
            int m = idx >> 2, q = idx & 3;
            cpa16(sbuf + m * BKP + q * 8,            Ahi + (size_t)m * lda + k0 + q * 8);
            cpa16(sbuf + BM * BKP + m * BKP + q * 8, Alo + (size_t)m * lda + k0 + q * 8);
        }
#pragma unroll
        for (int idx = tid; idx < BN * 4; idx += 256) {
            int n = idx >> 2, q = idx & 3;
            cpa16(sbuf + 2*BM*BKP + n * BKP + q * 8,          Bhi + (size_t)n * ldb + k0 + q * 8);
            cpa16(sbuf + 2*BM*BKP + BN*BKP + n * BKP + q * 8, Blo + (size_t)n * ldb + k0 + q * 8);
        }
    }

    __device__ static void run(const __nv_bfloat16* Ahi, const __nv_bfloat16* Alo, int lda,
                               const __nv_bfloat16* Bhi, const __nv_bfloat16* Blo, int ldb,
                               int K, float (&acc)[MT][NTT][4])
    {
        extern __shared__ unsigned char smem_raw[];
        __nv_bfloat16* sm = (__nv_bfloat16*)smem_raw;
        const int lane = threadIdx.x & 31;
        const int wid  = threadIdx.x >> 5;
        const int wrow = wid / WN, wcol = wid % WN;
#pragma unroll
        for (int i = 0; i < MT; i++)
#pragma unroll
            for (int j = 0; j < NTT; j++)
#pragma unroll
                for (int e = 0; e < 4; e++) acc[i][j][e] = 0.f;

        const int arow0 = wrow * (MT * 16) + (lane & 15);
        const int acolL = (lane >> 4) * 8;
        const int bg    = lane >> 3;
        const int brow0 = wcol * (NTT * 8) + ((bg >> 1) << 3) + (lane & 7);
        const int bcolL = (bg & 1) << 3;

        const int iters = K / BK;
        prefetch(Ahi, Alo, lda, Bhi, Blo, ldb, 0, sm);
        cp_commit();
        for (int it = 0; it < iters; it++) {
            if (it + 1 < iters) {
                prefetch(Ahi, Alo, lda, Bhi, Blo, ldb, (it + 1) * BK, sm + ((it + 1) & 1) * STAGE);
                cp_commit();
                cp_wait1();
            } else {
                cp_wait0();
            }
            __syncthreads();
            const __nv_bfloat16* buf  = sm + (it & 1) * STAGE;
            const __nv_bfloat16* sAhi = buf;
            const __nv_bfloat16* sAlo = buf + BM * BKP;
            const __nv_bfloat16* sBhi = buf + 2 * BM * BKP;
            const __nv_bfloat16* sBlo = buf + 2 * BM * BKP + BN * BKP;
#pragma unroll
            for (int kk = 0; kk < 2; kk++) {
                uint4 ahi[MT], alo[MT];
#pragma unroll
                for (int i = 0; i < MT; i++) {
                    int off = (arow0 + i * 16) * BKP + kk * 16 + acolL;
                    ahi[i] = ldm4(sAhi + off);
                    alo[i] = ldm4(sAlo + off);
                }
#pragma unroll
                for (int jp = 0; jp < NTT / 2; jp++) {
                    int off = (brow0 + jp * 16) * BKP + kk * 16 + bcolL;
                    uint4 bhi = ldm4(sBhi + off);
                    uint4 blo = ldm4(sBlo + off);
#pragma unroll
                    for (int i = 0; i < MT; i++) {
                        mma_bf(acc[i][2*jp],   ahi[i], bhi.x, bhi.y);
                        mma_bf(acc[i][2*jp],   ahi[i], blo.x, blo.y);
                        mma_bf(acc[i][2*jp],   alo[i], bhi.x, bhi.y);
                        mma_bf(acc[i][2*jp+1], ahi[i], bhi.z, bhi.w);
                        mma_bf(acc[i][2*jp+1], ahi[i], blo.z, blo.w);
                        mma_bf(acc[i][2*jp+1], alo[i], bhi.z, bhi.w);
                    }
                }
            }
            __syncthreads();
        }
    }
};

// ---------------- 1) fused prep + weight conversion --------------------------
__global__ void kprepconv(const float* __restrict__ x,
                          const float* __restrict__ Wq, const float* __restrict__ Wk,
                          const float* __restrict__ Wv, const float* __restrict__ Wo)
{
    if (blockIdx.x < 4096) {
        int row = blockIdx.x;
        int b = row >> 9, t = row & 511;
        const float4* src = (const float4*)(x + (size_t)row * D_);
        int r2 = (b << 8) + (t >> 1);
        __nv_bfloat16* dh = ((t & 1) ? g_xbhi : g_xahi) + (size_t)r2 * D_;
        __nv_bfloat16* dl = ((t & 1) ? g_xblo : g_xalo) + (size_t)r2 * D_;
        int i = threadIdx.x;
        float4 v = src[i];
        float vv[4] = {v.x, v.y, v.z, v.w};
        __nv_bfloat16 hh[4], ll[4];
#pragma unroll
        for (int q = 0; q < 4; q++) bf16_split(vv[q], hh[q], ll[q]);
        __nv_bfloat162 t0, t1;
        t0.x = hh[0]; t0.y = hh[1]; t1.x = hh[2]; t1.y = hh[3];
        *(__nv_bfloat162*)(dh + i * 4)     = t0;
        *(__nv_bfloat162*)(dh + i * 4 + 2) = t1;
        t0.x = ll[0]; t0.y = ll[1]; t1.x = ll[2]; t1.y = ll[3];
        *(__nv_bfloat162*)(dl + i * 4)     = t0;
        *(__nv_bfloat162*)(dl + i * 4 + 2) = t1;

        float s = vv[0]*vv[0] + vv[1]*vv[1] + vv[2]*vv[2] + vv[3]*vv[3];
        __shared__ float red[8];
        for (int o = 16; o > 0; o >>= 1) s += __shfl_down_sync(0xffffffffu, s, o);
        if ((threadIdx.x & 31) == 0) red[threadIdx.x >> 5] = s;
        __syncthreads();
        if (threadIdx.x < 32) {
            float w = (threadIdx.x < 8) ? red[threadIdx.x] : 0.f;
            for (int o = 4; o > 0; o >>= 1) w += __shfl_down_sync(0xffffffffu, w, o);
            if (threadIdx.x == 0) g_inv[row] = 1.0f / fmaxf(sqrtf(w), 1e-12f);
        }
        if (row < 128) g_hist[row * 256 + threadIdx.x] = 0;
        if (row == 0 && threadIdx.x < B_) g_done[threadIdx.x] = 0;
    } else {
        int idx = blockIdx.x - 4096;
        int mat = idx >> 10, blk = idx & 1023;
        const float* W = (mat == 0) ? Wq : (mat == 1) ? Wk : (mat == 2) ? Wv : Wo;
        size_t base = (size_t)mat * D_ * D_;
        int i = blk * 256 + threadIdx.x;
        float4 v = *(const float4*)(W + (size_t)i * 4);
        __half2 t0, t1;
        t0.x = __float2half_rn(v.x); t0.y = __float2half_rn(v.y);
        t1.x = __float2half_rn(v.z); t1.y = __float2half_rn(v.w);
        *(__half2*)(g_whi + base + (size_t)i * 4)     = t0;
        *(__half2*)(g_whi + base + (size_t)i * 4 + 2) = t1;
    }
}

// ---------------- 2) similarity via bf16 3-term mma (64x64 tiles) ------------
__global__ void __launch_bounds__(256) ksim_mma()
{
    using G = MmaGemmB<64,64,2,4>;
    int b = blockIdx.z;
    int a0 = blockIdx.y * 64, c0 = blockIdx.x * 64;
    float acc[G::MT][G::NTT][4];
    G::run(g_xahi + ((size_t)(b * TA_ + a0)) * D_, g_xalo + ((size_t)(b * TA_ + a0)) * D_, D_,
           g_xbhi + ((size_t)(b * TB_ + c0)) * D_, g_xblo + ((size_t)(b * TB_ + c0)) * D_, D_,
           D_, acc);

    int lane = threadIdx.x & 31, wid = threadIdx.x >> 5;
    int wrow = wid / 4, wcol = wid % 4;
    int g = lane >> 2, t4 = lane & 3;
#pragma unroll
    for (int i = 0; i < G::MT; i++)
#pragma unroll
        for (int j = 0; j < G::NTT; j++)
#pragma unroll
            for (int e = 0; e < 4; e++) {
                int a = a0 + wrow * 32 + i * 16 + g + ((e >> 1) << 3);
                int c = c0 + wcol * 16 + j * 8 + 2 * t4 + (e & 1);
                float v = acc[i][j][e] * g_inv[b * T_ + 2 * a] * g_inv[b * T_ + 2 * c + 1];
                unsigned u = __float_as_uint(v);
                unsigned ord = u ^ ((u & 0x80000000u) ? 0xFFFFFFFFu : 0x80000000u);
                unsigned flat = (unsigned)(a * TB_ + c);
                g_keys[(size_t)b * NPAIR + flat] =
                    ((unsigned long long)ord << 32) | (unsigned)(~flat);
            }
}

// ---------------- 3) histogram + last-block threshold ------------------------
__global__ void khistcut()
{
    __shared__ int h[4096];
    __shared__ int strip[256];
    __shared__ int suffix[257];
    __shared__ int isLast;
    int chunk = blockIdx.x, b = blockIdx.y, tid = threadIdx.x;
    for (int i = tid; i < 4096; i += 256) h[i] = 0;
    __syncthreads();
    const uint4* kv = (const uint4*)(g_keys + (size_t)b * NPAIR + chunk * 8192);
#pragma unroll 4
    for (int i = tid; i < 4096; i += 256) {
        uint4 v = kv[i];
        atomicAdd(&h[v.y >> 20], 1);
        atomicAdd(&h[v.w >> 20], 1);
    }
    __syncthreads();
    for (int i = tid; i < 4096; i += 256) {
        int v = h[i];
        if (v) atomicAdd(&g_hist[b * 4096 + i], v);
    }
    __threadfence();
    if (tid == 0) isLast = (atomicAdd(&g_done[b], 1) == 7);
    __syncthreads();
    if (!isLast) return;

    // last block for this b: compute threshold
    for (int i = tid; i < 4096; i += 256) h[i] = g_hist[b * 4096 + i];
    __syncthreads();
    int s = 0;
#pragma unroll
    for (int k = 0; k < 16; k++) s += h[tid * 16 + k];
    strip[tid] = s;
    __syncthreads();
    if (tid == 0) {
        int acc = 0;
        suffix[256] = 0;
        for (int i = 255; i >= 0; i--) { acc += strip[i]; suffix[i] = acc; }
    }
    __syncthreads();
    if (suffix[tid] >= 1024 && suffix[tid + 1] < 1024) {
        int c = suffix[tid + 1];
        int cut = tid * 16;
        for (int bkt = tid * 16 + 15; bkt >= tid * 16; bkt--) {
            c += h[bkt];
            if (c >= 1024) { cut = bkt; break; }
        }
        g_cut[b] = cut;
    }
}

// ---------------- 4) compact (inline) + sort + exact greedy match ------------
__device__ __forceinline__ void bitonic_sort_desc(unsigned long long* sk, int N, int tid, int nt)
{
    for (int k = 2; k <= N; k <<= 1) {
        for (int j = k >> 1; j > 0; j >>= 1) {
            for (int i = tid; i < N; i += nt) {
                int ixj = i ^ j;
                if (ixj > i) {
                    bool dir = ((i & k) == 0);
                    unsigned long long x0 = sk[i], x1 = sk[ixj];
                    if (dir ? (x0 < x1) : (x0 > x1)) { sk[i] = x1; sk[ixj] = x0; }
                }
            }
            __syncthreads();
        }
    }
}

__global__ void ksortgreedy()
{
    extern __shared__ unsigned char smem_raw[];
    unsigned long long* sk = (unsigned long long*)smem_raw;
    __shared__ int cnt;
    int b = blockIdx.x, tid = threadIdx.x;
    if (tid == 0) cnt = 0;
    __syncthreads();
    int cut = g_cut[b];
    const unsigned long long* keys = g_keys + (size_t)b * NPAIR;
#pragma unroll 4
    for (int i = tid; i < NPAIR; i += 1024) {
        unsigned long long k = keys[i];
        if ((int)(k >> 52) >= cut) {
            int pos = atomicAdd(&cnt, 1);
            if (pos < NCAP) sk[pos] = k;
        }
    }
    __syncthreads();
    int c = cnt; if (c > NCAP) c = NCAP;
    for (int i = tid; i < NCAP; i += 1024)
        if (i >= c) sk[i] = 0ull;
    __syncthreads();
    bitonic_sort_desc(sk, NCAP, tid, 1024);
    if (tid == 0) {
        unsigned char ua[TA_], ub[TB_];
        int partner[TA_];
        for (int i = 0; i < TA_; i++) { ua[i] = 0; partner[i] = -1; }
        for (int i = 0; i < TB_; i++) ub[i] = 0;
        int m = 0;
        for (int i = 0; i < c && m < R_; i++) {
            unsigned flat = ~(unsigned)sk[i];
            int a = (int)(flat >> 8), cc = (int)(flat & 255u);
            if (!ua[a] && !ub[cc]) { ua[a] = 1; ub[cc] = 1; partner[a] = cc; m++; }
        }
        for (int i = 0; i < TA_; i++) {
            int p = partner[i];
            g_srcA[b * TM_ + i] = 2 * i;
            g_srcB[b * TM_ + i] = (p >= 0) ? (2 * p + 1) : -1;
            g_dst0[b * TM_ + i] = 2 * i;
            g_dst1[b * TM_ + i] = (p >= 0) ? (2 * p + 1) : -1;
        }
        int j = 0;
        for (int cc = 0; cc < TB_; cc++) if (!ub[cc]) {
            int mm = TA_ + j;
            g_srcA[b * TM_ + mm] = 2 * cc + 1;
            g_srcB[b * TM_ + mm] = -1;
            g_dst0[b * TM_ + mm] = 2 * cc + 1;
            g_dst1[b * TM_ + mm] = -1;
            j++;
        }
    }
}

// ---------------- 5) merged sequence -> fp16 hi/lo ---------------------------
__global__ void kmerge(const float* __restrict__ x)
{
    int bm = blockIdx.x;
    int b = bm / TM_;
    int sA = g_srcA[bm], sB = g_srcB[bm];
    const float4* pa = (const float4*)(x + ((size_t)(b * T_ + sA)) * D_);
    const float4* pb = (sB >= 0) ? (const float4*)(x + ((size_t)(b * T_ + sB)) * D_) : nullptr;
    __half* mhi = g_mhi + (size_t)bm * D_;
    __half* mlo = g_mlo + (size_t)bm * D_;
    for (int i = threadIdx.x; i < D_ / 4; i += blockDim.x) {
        float4 a = pa[i];
        float v[4] = {a.x, a.y, a.z, a.w};
        if (pb) {
            float4 c = pb[i];
            v[0] = 0.5f * (v[0] + c.x); v[1] = 0.5f * (v[1] + c.y);
            v[2] = 0.5f * (v[2] + c.z); v[3] = 0.5f * (v[3] + c.w);
        }
        __half hh[4], ll[4];
#pragma unroll
        for (int q = 0; q < 4; q++) fp16_split(v[q], hh[q], ll[q]);
        __half2 t0, t1;
        t0.x = hh[0]; t0.y = hh[1]; t1.x = hh[2]; t1.y = hh[3];
        *(__half2*)(mhi + i * 4)     = t0;
        *(__half2*)(mhi + i * 4 + 2) = t1;
        t0.x = ll[0]; t0.y = ll[1]; t1.x = ll[2]; t1.y = ll[3];
        *(__half2*)(mlo + i * 4)     = t0;
        *(__half2*)(mlo + i * 4 + 2) = t1;
    }
}

// ---------------- 6) fused Q/K/V projection (z=0: 2-term; z=1,2: 1-term) -----
__global__ void __launch_bounds__(256) kqkv()
{
    int z = blockIdx.z;
    int m0 = blockIdx.y * 128, n0 = blockIdx.x * 128;
    int lane = threadIdx.x & 31, wid = threadIdx.x >> 5;
    int wrow = wid / 2, wcol = wid % 2;
    int g = lane >> 2, t4 = lane & 3;

    if (z == 0) {
        using G = MmaGemmH<128,128,4,2,true>;
        const __half* Bhi = g_whi + (size_t)n0 * D_;
        float acc[G::MT][G::NTT][4];
        G::run(g_mhi + (size_t)m0 * D_, g_mlo + (size_t)m0 * D_, D_, Bhi, D_, D_, acc);
#pragma unroll
        for (int i = 0; i < G::MT; i++)
#pragma unroll
            for (int rr = 0; rr < 2; rr++) {
                int m = m0 + wrow * 32 + i * 16 + g + rr * 8;
                int b = m / TM_, t = m % TM_;
#pragma unroll
                for (int j = 0; j < G::NTT; j++) {
                    int n = n0 + wcol * 64 + j * 8 + 2 * t4;
                    int h = n >> 6, d = n & 63;
                    size_t base = (((size_t)(b * H_ + h)) * TM_ + t) * HD_ + d;
                    __half h0, l0, h1, l1;
                    fp16_split(acc[i][j][rr * 2] * 0.125f, h0, l0);
                    fp16_split(acc[i][j][rr * 2 + 1] * 0.125f, h1, l1);
                    __half2 th, tl;
                    th.x = h0; th.y = h1; *(__half2*)(g_qhi + base) = th;
                    tl.x = l0; tl.y = l1; *(__half2*)(g_qlo + base) = tl;
                }
            }
    } else {
        using G = MmaGemmH<128,128,4,2,false>;
        const __half* Bhi = g_whi + (size_t)z * D_ * D_ + (size_t)n0 * D_;
        float acc[G::MT][G::NTT][4];
        G::run(g_mhi + (size_t)m0 * D_, nullptr, D_, Bhi, D_, D_, acc);
        __half* Dst = (z == 1) ? g_khi : g_vhi;
#pragma unroll
        for (int i = 0; i < G::MT; i++)
#pragma unroll
            for (int rr = 0; rr < 2; rr++) {
                int m = m0 + wrow * 32 + i * 16 + g + rr * 8;
                int b = m / TM_, t = m % TM_;
#pragma unroll
                for (int j = 0; j < G::NTT; j++) {
                    int n = n0 + wcol * 64 + j * 8 + 2 * t4;
                    int h = n >> 6, d = n & 63;
                    size_t base = (((size_t)(b * H_ + h)) * TM_ + t) * HD_ + d;
                    __half2 th;
                    th.x = __float2half_rn(acc[i][j][rr * 2]);
                    th.y = __float2half_rn(acc[i][j][rr * 2 + 1]);
                    *(__half2*)(Dst + base) = th;
                }
            }
    }
}

// ---------------- 7) fused attention (fp16; P hi-only in PV) -----------------
#define ATTN_SMEM 98304
__global__ void __launch_bounds__(256) kattn()
{
    extern __shared__ unsigned char smem_raw[];
    __half* sm = (__half*)smem_raw;
    float* smax0 = (float*)(smem_raw + 97280);
    float* smax1 = smax0 + 64;
    float* ssum0 = smax0 + 128;
    float* ssum1 = smax0 + 192;

    const int bh = blockIdx.y;
    const int m0 = blockIdx.x * 64;
    const int tid = threadIdx.x, lane = tid & 31, wid = tid >> 5;
    const int wrow = wid >> 1, wcol = wid & 1;
    const int g = lane >> 2, t4 = lane & 3;

    __half* sQhi = sm;
    __half* sQlo = sm + 4608;
    __half* sKhi = sm + 9216;

    {
        const __half* qh = g_qhi + ((size_t)bh * TM_ + m0) * HD_;
        const __half* ql = g_qlo + ((size_t)bh * TM_ + m0) * HD_;
        for (int idx = tid; idx < 64 * 8; idx += 256) {
            int r = idx >> 3, q = idx & 7;
            *(uint4*)(sQhi + r * 72 + q * 8) = *(const uint4*)(qh + r * HD_ + q * 8);
            *(uint4*)(sQlo + r * 72 + q * 8) = *(const uint4*)(ql + r * HD_ + q * 8);
        }
        const __half* kh = g_khi + (size_t)bh * TM_ * HD_;
        for (int idx = tid; idx < 384 * 8; idx += 256) {
            int r = idx >> 3, q = idx & 7;
            *(uint4*)(sKhi + r * 72 + q * 8) = *(const uint4*)(kh + r * HD_ + q * 8);
        }
    }
    __syncthreads();

    float acc[24][4];
#pragma unroll
    for (int j = 0; j < 24; j++)
#pragma unroll
        for (int e = 0; e < 4; e++) acc[j][e] = 0.f;

    const int arow  = wrow * 16 + (lane & 15);
    const int acolL = (lane >> 4) * 8;
    const int bg    = lane >> 3;
    const int brow0 = wcol * 192 + ((bg >> 1) << 3) + (lane & 7);
    const int bcolL = (bg & 1) << 3;

#pragma unroll
    for (int kk = 0; kk < 4; kk++) {
        uint4 ahi = ldm4(sQhi + arow * 72 + kk * 16 + acolL);
        uint4 alo = ldm4(sQlo + arow * 72 + kk * 16 + acolL);
#pragma unroll
        for (int jp = 0; jp < 12; jp++) {
            int off = (brow0 + jp * 16) * 72 + kk * 16 + bcolL;
            uint4 bhi = ldm4(sKhi + off);
            mma_h(acc[2*jp],   ahi, bhi.x, bhi.y);
            mma_h(acc[2*jp],   alo, bhi.x, bhi.y);
            mma_h(acc[2*jp+1], ahi, bhi.z, bhi.w);
            mma_h(acc[2*jp+1], alo, bhi.z, bhi.w);
        }
    }

    const int r0 = wrow * 16 + g, r1 = r0 + 8;
    float mx0 = -1e30f, mx1 = -1e30f;
#pragma unroll
    for (int j = 0; j < 24; j++) {
        mx0 = fmaxf(mx0, fmaxf(acc[j][0], acc[j][1]));
        mx1 = fmaxf(mx1, fmaxf(acc[j][2], acc[j][3]));
    }
    mx0 = fmaxf(mx0, __shfl_xor_sync(0xffffffffu, mx0, 1));
    mx0 = fmaxf(mx0, __shfl_xor_sync(0xffffffffu, mx0, 2));
    mx1 = fmaxf(mx1, __shfl_xor_sync(0xffffffffu, mx1, 1));
    mx1 = fmaxf(mx1, __shfl_xor_sync(0xffffffffu, mx1, 2));
    if (t4 == 0) {
        (wcol ? smax1 : smax0)[r0] = mx0;
        (wcol ? smax1 : smax0)[r1] = mx1;
    }
    __syncthreads();
    float M0 = fmaxf(smax0[r0], smax1[r0]);
    float M1 = fmaxf(smax0[r1], smax1[r1]);
    float s0 = 0.f, s1 = 0.f;
#pragma unroll
    for (int j = 0; j < 24; j++) {
        acc[j][0] = expf(acc[j][0] - M0); s0 += acc[j][0];
        acc[j][1] = expf(acc[j][1] - M0); s0 += acc[j][1];
        acc[j][2] = expf(acc[j][2] - M1); s1 += acc[j][2];
        acc[j][3] = expf(acc[j][3] - M1); s1 += acc[j][3];
    }
    s0 += __shfl_xor_sync(0xffffffffu, s0, 1); s0 += __shfl_xor_sync(0xffffffffu, s0, 2);
    s1 += __shfl_xor_sync(0xffffffffu, s1, 1); s1 += __shfl_xor_sync(0xffffffffu, s1, 2);
    if (t4 == 0) {
        (wcol ? ssum1 : ssum0)[r0] = s0;
        (wcol ? ssum1 : ssum0)[r1] = s1;
    }
    __syncthreads();

    {
        __half* sPhi = sm + 9216 + wcol * 12800;
#pragma unroll
        for (int j = 0; j < 24; j++) {
            int col = j * 8 + 2 * t4;
            __half2 th;
            th.x = __float2half_rn(acc[j][0]);
            th.y = __float2half_rn(acc[j][1]);
            *(__half2*)(sPhi + r0 * 200 + col) = th;
            th.x = __float2half_rn(acc[j][2]);
            th.y = __float2half_rn(acc[j][3]);
            *(__half2*)(sPhi + r1 * 200 + col) = th;
        }
    }
    __syncthreads();

    float acc2[4][4];
#pragma unroll
    for (int j = 0; j < 4; j++)
#pragma unroll
        for (int e = 0; e < 4; e++) acc2[j][e] = 0.f;

    __half* sVhi = sm + 34816;
    const int arow2 = wrow * 16 + (lane & 15);
    const int vrowL = ((bg & 1) << 3) + (lane & 7);
    const int vcolL = (bg >> 1) << 3;

    for (int c = 0; c < 2; c++) {
        if (c) __syncthreads();
        const __half* vh = g_vhi + ((size_t)bh * TM_ + c * 192) * HD_;
        for (int idx = tid; idx < 192 * 8; idx += 256) {
            int r = idx >> 3, q = idx & 7;
            *(uint4*)(sVhi + r * 72 + q * 8) = *(const uint4*)(vh + r * HD_ + q * 8);
        }
        __syncthreads();
        const __half* cPhi = sm + 9216 + c * 12800;
#pragma unroll
        for (int kk = 0; kk < 12; kk++) {
            uint4 phi = ldm4(cPhi + arow2 * 200 + kk * 16 + acolL);
#pragma unroll
            for (int jp = 0; jp < 2; jp++) {
                int off = (kk * 16 + vrowL) * 72 + wcol * 32 + jp * 16 + vcolL;
                uint4 vhi = ldm4t(sVhi + off);
                mma_h(acc2[2*jp],   phi, vhi.x, vhi.y);
                mma_h(acc2[2*jp+1], phi, vhi.z, vhi.w);
            }
        }
    }

    const int b = bh >> 4, hh = bh & 15;
    const float inv0 = 1.0f / (ssum0[r0] + ssum1[r0]);
    const float inv1 = 1.0f / (ssum0[r1] + ssum1[r1]);
#pragma unroll
    for (int j = 0; j < 4; j++) {
        int col = (wid & 1) * 32 + j * 8 + 2 * t4;
        int t  = m0 + r0;
        size_t o0 = ((size_t)(b * TM_ + t)) * D_ + hh * HD_ + col;
        size_t o1 = ((size_t)(b * TM_ + t + 8)) * D_ + hh * HD_ + col;
        __half h0, l0, h1, l1;
        __half2 th, tl;
        fp16_split(acc2[j][0] * inv0, h0, l0); fp16_split(acc2[j][1] * inv0, h1, l1);
        th.x = h0; th.y = h1; *(__half2*)(g_ahi + o0) = th;
        tl.x = l0; tl.y = l1; *(__half2*)(g_alo + o0) = tl;
        fp16_split(acc2[j][2] * inv1, h0, l0); fp16_split(acc2[j][3] * inv1, h1, l1);
        th.x = h0; th.y = h1; *(__half2*)(g_ahi + o1) = th;
        tl.x = l0; tl.y = l1; *(__half2*)(g_alo + o1) = tl;
    }
}

// ---------------- 8) output projection + fused unmerge scatter --------------
__global__ void __launch_bounds__(256) kout(float* __restrict__ out)
{
    using G = MmaGemmH<128,128,4,2,true>;
    int m0 = blockIdx.y * 128, n0 = blockIdx.x * 128;
    const __half* Bhi = g_whi + (size_t)3 * D_ * D_ + (size_t)n0 * D_;
    float acc[G::MT][G::NTT][4];
    G::run(g_ahi + (size_t)m0 * D_, g_alo + (size_t)m0 * D_, D_, Bhi, D_, D_, acc);

    int lane = threadIdx.x & 31, wid = threadIdx.x >> 5;
    int wrow = wid / 2, wcol = wid % 2;
    int g = lane >> 2, t4 = lane & 3;
#pragma unroll
    for (int i = 0; i < G::MT; i++) {
#pragma unroll
        for (int rr = 0; rr < 2; rr++) {
            int m = m0 + wrow * 32 + i * 16 + g + rr * 8;
            int b = m / TM_, mm = m % TM_;
            int d0 = g_dst0[b * TM_ + mm];
            int d1 = g_dst1[b * TM_ + mm];
#pragma unroll
            for (int j = 0; j < G::NTT; j++) {
                int n = n0 + wcol * 64 + j * 8 + 2 * t4;
                float2 v = make_float2(acc[i][j][rr * 2], acc[i][j][rr * 2 + 1]);
                *(float2*)&out[((size_t)(b * T_ + d0)) * D_ + n] = v;
                if (d1 >= 0) *(float2*)&out[((size_t)(b * T_ + d1)) * D_ + n] = v;
            }
        }
    }
}

// ---------------- launcher ----------------------------------------------------
extern "C" void kernel_launch(void* const* d_in, const int* in_sizes, int n_in,
                              void* d_out, int out_size)
{
    const float* x  = (const float*)d_in[0];
    const float* Wq = (const float*)d_in[1];
    const float* Wk = (const float*)d_in[2];
    const float* Wv = (const float*)d_in[3];
    const float* Wo = (const float*)d_in[4];
    float* out = (float*)d_out;

    const int smem_h2 = MmaGemmH<128,128,4,2,true>::SMEM;   // 110592
    const int smem_b  = MmaGemmB<64,64,2,4>::SMEM;          // 40960

    cudaFuncSetAttribute(kqkv,     cudaFuncAttributeMaxDynamicSharedMemorySize, smem_h2);
    cudaFuncSetAttribute(kout,     cudaFuncAttributeMaxDynamicSharedMemorySize, smem_h2);
    cudaFuncSetAttribute(ksim_mma, cudaFuncAttributeMaxDynamicSharedMemorySize, smem_b);
    cudaFuncSetAttribute(kattn,    cudaFuncAttributeMaxDynamicSharedMemorySize, ATTN_SMEM);

    kprepconv<<<8192, 256>>>(x, Wq, Wk, Wv, Wo);
    ksim_mma<<<dim3(4, 4, B_), 256, smem_b>>>();
    khistcut<<<dim3(8, B_), 256>>>();
    ksortgreedy<<<B_, 1024, NCAP * 8>>>();
    kmerge<<<B_ * TM_, 256>>>(x);
    kqkv<<<dim3(8, 24, 3), 256, smem_h2>>>();
    kattn<<<dim3(6, B_ * H_), 256, ATTN_SMEM>>>();
    kout<<<dim3(8, 24), 256, smem_h2>>>(out);
}

// round 12
// speedup vs baseline: 1.2097x; 1.0533x over previous
#include <cuda_runtime.h>
#include <cuda_bf16.h>
#include <cuda_fp16.h>
#include <math.h>
#include <stdint.h>

#define B_   8
#define T_   512
#define D_   1024
#define H_   16
#define HD_  64
#define TA_  256
#define TB_  256
#define R_   128
#define TM_  384
#define NPAIR 65536
#define NCAP  2048

// ---------------- scratch (device globals) -----------------------------------
__device__ float              g_inv [B_*T_];
__device__ __align__(16) unsigned long long g_keys[B_*NPAIR];
__device__ int                g_hist[B_*4096];
__device__ int                g_done[B_];
__device__ int                g_cut [B_];
__device__ int                g_srcA[B_*TM_];
__device__ int                g_srcB[B_*TM_];
__device__ int                g_dst0[B_*TM_];
__device__ int                g_dst1[B_*TM_];
// fp16 operands (A side hi/lo, B side hi only)
__device__ __align__(16) __half g_mhi [B_*TM_*D_];
__device__ __align__(16) __half g_mlo [B_*TM_*D_];
__device__ __align__(16) __half g_whi [4*D_*D_];
__device__ __align__(16) __half g_qhi [B_*H_*TM_*HD_];
__device__ __align__(16) __half g_qlo [B_*H_*TM_*HD_];
__device__ __align__(16) __half g_khi [B_*H_*TM_*HD_];
__device__ __align__(16) __half g_vhi [B_*H_*TM_*HD_];
__device__ __align__(16) __half g_ahi [B_*TM_*D_];
__device__ __align__(16) __half g_alo [B_*TM_*D_];
// packed even/odd token sets for similarity mma (bf16 3-term, exact-order path)
__device__ __align__(16) __nv_bfloat16 g_xahi[B_*TA_*D_];
__device__ __align__(16) __nv_bfloat16 g_xalo[B_*TA_*D_];
__device__ __align__(16) __nv_bfloat16 g_xbhi[B_*TB_*D_];
__device__ __align__(16) __nv_bfloat16 g_xblo[B_*TB_*D_];

// ---------------- helpers -----------------------------------------------------
__device__ __forceinline__ void bf16_split(float v, __nv_bfloat16& h, __nv_bfloat16& l)
{
    h = __float2bfloat16(v);
    l = __float2bfloat16(v - __bfloat162float(h));
}

__device__ __forceinline__ void fp16_split(float v, __half& h, __half& l)
{
    h = __float2half_rn(v);
    l = __float2half_rn(v - __half2float(h));
}

__device__ __forceinline__ uint4 ldm4(const void* p)
{
    uint4 r; unsigned a = (unsigned)__cvta_generic_to_shared(p);
    asm volatile("ldmatrix.sync.aligned.m8n8.x4.shared.b16 {%0,%1,%2,%3}, [%4];"
        : "=r"(r.x), "=r"(r.y), "=r"(r.z), "=r"(r.w) : "r"(a));
    return r;
}

__device__ __forceinline__ uint4 ldm4t(const void* p)
{
    uint4 r; unsigned a = (unsigned)__cvta_generic_to_shared(p);
    asm volatile("ldmatrix.sync.aligned.m8n8.x4.trans.shared.b16 {%0,%1,%2,%3}, [%4];"
        : "=r"(r.x), "=r"(r.y), "=r"(r.z), "=r"(r.w) : "r"(a));
    return r;
}

__device__ __forceinline__ void mma_bf(float* c, uint4 a, unsigned b0, unsigned b1)
{
    asm volatile("mma.sync.aligned.m16n8k16.row.col.f32.bf16.bf16.f32 "
        "{%0,%1,%2,%3},{%4,%5,%6,%7},{%8,%9},{%0,%1,%2,%3};"
        : "+f"(c[0]), "+f"(c[1]), "+f"(c[2]), "+f"(c[3])
        : "r"(a.x), "r"(a.y), "r"(a.z), "r"(a.w), "r"(b0), "r"(b1));
}

__device__ __forceinline__ void mma_h(float* c, uint4 a, unsigned b0, unsigned b1)
{
    asm volatile("mma.sync.aligned.m16n8k16.row.col.f32.f16.f16.f32 "
        "{%0,%1,%2,%3},{%4,%5,%6,%7},{%8,%9},{%0,%1,%2,%3};"
        : "+f"(c[0]), "+f"(c[1]), "+f"(c[2]), "+f"(c[3])
        : "r"(a.x), "r"(a.y), "r"(a.z), "r"(a.w), "r"(b0), "r"(b1));
}

__device__ __forceinline__ void cpa16(void* dst, const void* src)
{
    unsigned d = (unsigned)__cvta_generic_to_shared(dst);
    asm volatile("cp.async.ca.shared.global [%0], [%1], 16;" :: "r"(d), "l"(src));
}
__device__ __forceinline__ void cp_commit() { asm volatile("cp.async.commit_group;"); }
__device__ __forceinline__ void cp_wait1()  { asm volatile("cp.async.wait_group 1;"); }
__device__ __forceinline__ void cp_wait0()  { asm volatile("cp.async.wait_group 0;"); }

// ====== fp16 GEMM, BK=64: C = (Ahi[+Alo]) · Bhi^T =============================
template<int BM, int BN, int WM, int WN, bool ALO>
struct MmaGemmH {
    static constexpr int MT  = BM / WM / 16;
    static constexpr int NTT = BN / WN / 8;
    static constexpr int BK  = 64;
    static constexpr int BKP = 72;
    static constexpr int AROWS = ALO ? 2 * BM : BM;
    static constexpr int STAGE = (AROWS + BN) * BKP;     // half elems per stage
    static constexpr int SMEM  = 2 * STAGE * 2;          // bytes

    __device__ static void prefetch(const __half* Ahi, const __half* Alo, int lda,
                                    const __half* Bhi, int ldb, int k0, __half* sbuf)
    {
        const int tid = threadIdx.x;
#pragma unroll
        for (int idx = tid; idx < BM * 8; idx += 256) {
            int m = idx >> 3, q = idx & 7;
            cpa16(sbuf + m * BKP + q * 8, Ahi + (size_t)m * lda + k0 + q * 8);
            if (ALO)
                cpa16(sbuf + BM * BKP + m * BKP + q * 8, Alo + (size_t)m * lda + k0 + q * 8);
        }
#pragma unroll
        for (int idx = tid; idx < BN * 8; idx += 256) {
            int n = idx >> 3, q = idx & 7;
            cpa16(sbuf + AROWS * BKP + n * BKP + q * 8, Bhi + (size_t)n * ldb + k0 + q * 8);
        }
    }

    __device__ static void run(const __half* Ahi, const __half* Alo, int lda,
                               const __half* Bhi, int ldb,
                               int K, float (&acc)[MT][NTT][4])
    {
        extern __shared__ unsigned char smem_raw[];
        __half* sm = (__half*)smem_raw;
        const int lane = threadIdx.x & 31;
        const int wid  = threadIdx.x >> 5;
        const int wrow = wid / WN, wcol = wid % WN;
#pragma unroll
        for (int i = 0; i < MT; i++)
#pragma unroll
            for (int j = 0; j < NTT; j++)
#pragma unroll
                for (int e = 0; e < 4; e++) acc[i][j][e] = 0.f;

        const int arow0 = wrow * (MT * 16) + (lane & 15);
        const int acolL = (lane >> 4) * 8;
        const int bg    = lane >> 3;
        const int brow0 = wcol * (NTT * 8) + ((bg >> 1) << 3) + (lane & 7);
        const int bcolL = (bg & 1) << 3;

        const int iters = K / BK;
        prefetch(Ahi, Alo, lda, Bhi, ldb, 0, sm);
        cp_commit();
        for (int it = 0; it < iters; it++) {
            if (it + 1 < iters) {
                prefetch(Ahi, Alo, lda, Bhi, ldb, (it + 1) * BK, sm + ((it + 1) & 1) * STAGE);
                cp_commit();
                cp_wait1();
            } else {
                cp_wait0();
            }
            __syncthreads();
            const __half* buf  = sm + (it & 1) * STAGE;
            const __half* sAhi = buf;
            const __half* sAlo = buf + BM * BKP;
            const __half* sBhi = buf + AROWS * BKP;
#pragma unroll
            for (int kk = 0; kk < 4; kk++) {
                uint4 ahi[MT], alo[MT];
#pragma unroll
                for (int i = 0; i < MT; i++) {
                    int off = (arow0 + i * 16) * BKP + kk * 16 + acolL;
                    ahi[i] = ldm4(sAhi + off);
                    if (ALO) alo[i] = ldm4(sAlo + off);
                }
#pragma unroll
                for (int jp = 0; jp < NTT / 2; jp++) {
                    int off = (brow0 + jp * 16) * BKP + kk * 16 + bcolL;
                    uint4 bhi = ldm4(sBhi + off);
#pragma unroll
                    for (int i = 0; i < MT; i++) {
                        mma_h(acc[i][2*jp],   ahi[i], bhi.x, bhi.y);
                        if (ALO) mma_h(acc[i][2*jp], alo[i], bhi.x, bhi.y);
                        mma_h(acc[i][2*jp+1], ahi[i], bhi.z, bhi.w);
                        if (ALO) mma_h(acc[i][2*jp+1], alo[i], bhi.z, bhi.w);
                    }
                }
            }
            __syncthreads();
        }
    }
};

// ====== bf16 3-term GEMM (similarity / exact-order path only) =================
template<int BM, int BN, int WM, int WN>
struct MmaGemmB {
    static constexpr int MT  = BM / WM / 16;
    static constexpr int NTT = BN / WN / 8;
    static constexpr int BK  = 32;
    static constexpr int BKP = 40;
    static constexpr int STAGE = (BM + BN) * 2 * BKP;
    static constexpr int SMEM  = 2 * STAGE * 2;

    __device__ static void prefetch(const __nv_bfloat16* Ahi, const __nv_bfloat16* Alo, int lda,
                                    const __nv_bfloat16* Bhi, const __nv_bfloat16* Blo, int ldb,
                                    int k0, __nv_bfloat16* sbuf)
    {
        const int tid = threadIdx.x;
#pragma unroll
        for (int idx = tid; idx < BM * 4; idx += 256) {
            int m = idx >> 2, q = idx & 3;
            cpa16(sbuf + m * BKP + q * 8,            Ahi + (size_t)m * lda + k0 + q * 8);
            cpa16(sbuf + BM * BKP + m * BKP + q * 8, Alo + (size_t)m * lda + k0 + q * 8);
        }
#pragma unroll
        for (int idx = tid; idx < BN * 4; idx += 256) {
            int n = idx >> 2, q = idx & 3;
            cpa16(sbuf + 2*BM*BKP + n * BKP + q * 8,          Bhi + (size_t)n * ldb + k0 + q * 8);
            cpa16(sbuf + 2*BM*BKP + BN*BKP + n * BKP + q * 8, Blo + (size_t)n * ldb + k0 + q * 8);
        }
    }

    __device__ static void run(const __nv_bfloat16* Ahi, const __nv_bfloat16* Alo, int lda,
                               const __nv_bfloat16* Bhi, const __nv_bfloat16* Blo, int ldb,
                               int K, float (&acc)[MT][NTT][4])
    {
        extern __shared__ unsigned char smem_raw[];
        __nv_bfloat16* sm = (__nv_bfloat16*)smem_raw;
        const int lane = threadIdx.x & 31;
        const int wid  = threadIdx.x >> 5;
        const int wrow = wid / WN, wcol = wid % WN;
#pragma unroll
        for (int i = 0; i < MT; i++)
#pragma unroll
            for (int j = 0; j < NTT; j++)
#pragma unroll
                for (int e = 0; e < 4; e++) acc[i][j][e] = 0.f;

        const int arow0 = wrow * (MT * 16) + (lane & 15);
        const int acolL = (lane >> 4) * 8;
        const int bg    = lane >> 3;
        const int brow0 = wcol * (NTT * 8) + ((bg >> 1) << 3) + (lane & 7);
        const int bcolL = (bg & 1) << 3;

        const int iters = K / BK;
        prefetch(Ahi, Alo, lda, Bhi, Blo, ldb, 0, sm);
        cp_commit();
        for (int it = 0; it < iters; it++) {
            if (it + 1 < iters) {
                prefetch(Ahi, Alo, lda, Bhi, Blo, ldb, (it + 1) * BK, sm + ((it + 1) & 1) * STAGE);
                cp_commit();
                cp_wait1();
            } else {
                cp_wait0();
            }
            __syncthreads();
            const __nv_bfloat16* buf  = sm + (it & 1) * STAGE;
            const __nv_bfloat16* sAhi = buf;
            const __nv_bfloat16* sAlo = buf + BM * BKP;
            const __nv_bfloat16* sBhi = buf + 2 * BM * BKP;
            const __nv_bfloat16* sBlo = buf + 2 * BM * BKP + BN * BKP;
#pragma unroll
            for (int kk = 0; kk < 2; kk++) {
                uint4 ahi[MT], alo[MT];
#pragma unroll
                for (int i = 0; i < MT; i++) {
                    int off = (arow0 + i * 16) * BKP + kk * 16 + acolL;
                    ahi[i] = ldm4(sAhi + off);
                    alo[i] = ldm4(sAlo + off);
                }
#pragma unroll
                for (int jp = 0; jp < NTT / 2; jp++) {
                    int off = (brow0 + jp * 16) * BKP + kk * 16 + bcolL;
                    uint4 bhi = ldm4(sBhi + off);
                    uint4 blo = ldm4(sBlo + off);
#pragma unroll
                    for (int i = 0; i < MT; i++) {
                        mma_bf(acc[i][2*jp],   ahi[i], bhi.x, bhi.y);
                        mma_bf(acc[i][2*jp],   ahi[i], blo.x, blo.y);
                        mma_bf(acc[i][2*jp],   alo[i], bhi.x, bhi.y);
                        mma_bf(acc[i][2*jp+1], ahi[i], bhi.z, bhi.w);
                        mma_bf(acc[i][2*jp+1], ahi[i], blo.z, blo.w);
                        mma_bf(acc[i][2*jp+1], alo[i], bhi.z, bhi.w);
                    }
                }
            }
            __syncthreads();
        }
    }
};

// ---------------- 1) fused prep + weight conversion --------------------------
__global__ void kprepconv(const float* __restrict__ x,
                          const float* __restrict__ Wq, const float* __restrict__ Wk,
                          const float* __restrict__ Wv, const float* __restrict__ Wo)
{
    if (blockIdx.x < 4096) {
        int row = blockIdx.x;
        int b = row >> 9, t = row & 511;
        const float4* src = (const float4*)(x + (size_t)row * D_);
        int r2 = (b << 8) + (t >> 1);
        __nv_bfloat16* dh = ((t & 1) ? g_xbhi : g_xahi) + (size_t)r2 * D_;
        __nv_bfloat16* dl = ((t & 1) ? g_xblo : g_xalo) + (size_t)r2 * D_;
        int i = threadIdx.x;
        float4 v = src[i];
        float vv[4] = {v.x, v.y, v.z, v.w};
        __nv_bfloat16 hh[4], ll[4];
#pragma unroll
        for (int q = 0; q < 4; q++) bf16_split(vv[q], hh[q], ll[q]);
        __nv_bfloat162 t0, t1;
        t0.x = hh[0]; t0.y = hh[1]; t1.x = hh[2]; t1.y = hh[3];
        *(__nv_bfloat162*)(dh + i * 4)     = t0;
        *(__nv_bfloat162*)(dh + i * 4 + 2) = t1;
        t0.x = ll[0]; t0.y = ll[1]; t1.x = ll[2]; t1.y = ll[3];
        *(__nv_bfloat162*)(dl + i * 4)     = t0;
        *(__nv_bfloat162*)(dl + i * 4 + 2) = t1;

        float s = vv[0]*vv[0] + vv[1]*vv[1] + vv[2]*vv[2] + vv[3]*vv[3];
        __shared__ float red[8];
        for (int o = 16; o > 0; o >>= 1) s += __shfl_down_sync(0xffffffffu, s, o);
        if ((threadIdx.x & 31) == 0) red[threadIdx.x >> 5] = s;
        __syncthreads();
        if (threadIdx.x < 32) {
            float w = (threadIdx.x < 8) ? red[threadIdx.x] : 0.f;
            for (int o = 4; o > 0; o >>= 1) w += __shfl_down_sync(0xffffffffu, w, o);
            if (threadIdx.x == 0) g_inv[row] = 1.0f / fmaxf(sqrtf(w), 1e-12f);
        }
        if (row < 128) g_hist[row * 256 + threadIdx.x] = 0;
        if (row == 0 && threadIdx.x < B_) g_done[threadIdx.x] = 0;
    } else {
        int idx = blockIdx.x - 4096;
        int mat = idx >> 10, blk = idx & 1023;
        const float* W = (mat == 0) ? Wq : (mat == 1) ? Wk : (mat == 2) ? Wv : Wo;
        size_t base = (size_t)mat * D_ * D_;
        int i = blk * 256 + threadIdx.x;
        float4 v = *(const float4*)(W + (size_t)i * 4);
        __half2 t0, t1;
        t0.x = __float2half_rn(v.x); t0.y = __float2half_rn(v.y);
        t1.x = __float2half_rn(v.z); t1.y = __float2half_rn(v.w);
        *(__half2*)(g_whi + base + (size_t)i * 4)     = t0;
        *(__half2*)(g_whi + base + (size_t)i * 4 + 2) = t1;
    }
}

// ---------------- 2) similarity via bf16 3-term mma (64x64 tiles) ------------
__global__ void __launch_bounds__(256) ksim_mma()
{
    using G = MmaGemmB<64,64,2,4>;
    int b = blockIdx.z;
    int a0 = blockIdx.y * 64, c0 = blockIdx.x * 64;
    float acc[G::MT][G::NTT][4];
    G::run(g_xahi + ((size_t)(b * TA_ + a0)) * D_, g_xalo + ((size_t)(b * TA_ + a0)) * D_, D_,
           g_xbhi + ((size_t)(b * TB_ + c0)) * D_, g_xblo + ((size_t)(b * TB_ + c0)) * D_, D_,
           D_, acc);

    int lane = threadIdx.x & 31, wid = threadIdx.x >> 5;
    int wrow = wid / 4, wcol = wid % 4;
    int g = lane >> 2, t4 = lane & 3;
#pragma unroll
    for (int i = 0; i < G::MT; i++)
#pragma unroll
        for (int j = 0; j < G::NTT; j++)
#pragma unroll
            for (int e = 0; e < 4; e++) {
                int a = a0 + wrow * 32 + i * 16 + g + ((e >> 1) << 3);
                int c = c0 + wcol * 16 + j * 8 + 2 * t4 + (e & 1);
                float v = acc[i][j][e] * g_inv[b * T_ + 2 * a] * g_inv[b * T_ + 2 * c + 1];
                unsigned u = __float_as_uint(v);
                unsigned ord = u ^ ((u & 0x80000000u) ? 0xFFFFFFFFu : 0x80000000u);
                unsigned flat = (unsigned)(a * TB_ + c);
                g_keys[(size_t)b * NPAIR + flat] =
                    ((unsigned long long)ord << 32) | (unsigned)(~flat);
            }
}

// ---------------- 3) histogram + last-block threshold ------------------------
__global__ void khistcut()
{
    __shared__ int h[4096];
    __shared__ int strip[256];
    __shared__ int suffix[257];
    __shared__ int isLast;
    int chunk = blockIdx.x, b = blockIdx.y, tid = threadIdx.x;
    for (int i = tid; i < 4096; i += 256) h[i] = 0;
    __syncthreads();
    const uint4* kv = (const uint4*)(g_keys + (size_t)b * NPAIR + chunk * 8192);
#pragma unroll 4
    for (int i = tid; i < 4096; i += 256) {
        uint4 v = kv[i];
        atomicAdd(&h[v.y >> 20], 1);
        atomicAdd(&h[v.w >> 20], 1);
    }
    __syncthreads();
    for (int i = tid; i < 4096; i += 256) {
        int v = h[i];
        if (v) atomicAdd(&g_hist[b * 4096 + i], v);
    }
    __threadfence();
    if (tid == 0) isLast = (atomicAdd(&g_done[b], 1) == 7);
    __syncthreads();
    if (!isLast) return;

    for (int i = tid; i < 4096; i += 256) h[i] = g_hist[b * 4096 + i];
    __syncthreads();
    int s = 0;
#pragma unroll
    for (int k = 0; k < 16; k++) s += h[tid * 16 + k];
    strip[tid] = s;
    __syncthreads();
    if (tid == 0) {
        int acc = 0;
        suffix[256] = 0;
        for (int i = 255; i >= 0; i--) { acc += strip[i]; suffix[i] = acc; }
    }
    __syncthreads();
    if (suffix[tid] >= 1024 && suffix[tid + 1] < 1024) {
        int c = suffix[tid + 1];
        int cut = tid * 16;
        for (int bkt = tid * 16 + 15; bkt >= tid * 16; bkt--) {
            c += h[bkt];
            if (c >= 1024) { cut = bkt; break; }
        }
        g_cut[b] = cut;
    }
}

// ---------------- 4) compact + sort + warp-parallel exact greedy -------------
__device__ __forceinline__ void bitonic_sort_desc(unsigned long long* sk, int N, int tid, int nt)
{
    for (int k = 2; k <= N; k <<= 1) {
        for (int j = k >> 1; j > 0; j >>= 1) {
            for (int i = tid; i < N; i += nt) {
                int ixj = i ^ j;
                if (ixj > i) {
                    bool dir = ((i & k) == 0);
                    unsigned long long x0 = sk[i], x1 = sk[ixj];
                    if (dir ? (x0 < x1) : (x0 > x1)) { sk[i] = x1; sk[ixj] = x0; }
                }
            }
            __syncthreads();
        }
    }
}

#define SORT_SMEM (NCAP*8 + 512 + 256*4 + 256*4)
__global__ void ksortgreedy()
{
    extern __shared__ unsigned char smem_raw[];
    unsigned long long* sk = (unsigned long long*)smem_raw;          // NCAP keys
    unsigned char* ua = smem_raw + NCAP * 8;                         // 256
    unsigned char* ub = ua + 256;                                    // 256
    int* partner = (int*)(ub + 256);                                 // 256 ints
    int* scan    = partner + 256;                                    // 256 ints
    __shared__ int cnt;
    int b = blockIdx.x, tid = threadIdx.x;
    if (tid == 0) cnt = 0;
    if (tid < 256) { ua[tid] = 0; ub[tid] = 0; partner[tid] = -1; }
    __syncthreads();

    int cut = g_cut[b];
    const unsigned long long* keys = g_keys + (size_t)b * NPAIR;
#pragma unroll 4
    for (int i = tid; i < NPAIR; i += 1024) {
        unsigned long long k = keys[i];
        if ((int)(k >> 52) >= cut) {
            int pos = atomicAdd(&cnt, 1);
            if (pos < NCAP) sk[pos] = k;
        }
    }
    __syncthreads();
    int c = cnt; if (c > NCAP) c = NCAP;
    for (int i = tid; i < NCAP; i += 1024)
        if (i >= c) sk[i] = 0ull;
    __syncthreads();
    bitonic_sort_desc(sk, NCAP, tid, 1024);

    // warp 0: chunked greedy, identical order to the serial scan
    if (tid < 32) {
        int lane = tid;
        int m = 0;
        for (int base = 0; base < NCAP && m < R_; base += 32) {
            int idx = base + lane;
            unsigned long long k = sk[idx];
            unsigned flat = ~(unsigned)k;
            int a  = (int)((flat >> 8) & 255u);
            int cc = (int)(flat & 255u);
            bool avail = (idx < c) && !ua[a] && !ub[cc];
            unsigned availm = __ballot_sync(0xffffffffu, avail);
            unsigned taken = 0;
            for (int l = 0; l < 32; l++) {
                if (m >= R_) break;
                if (!((availm >> l) & 1)) continue;
                int aa  = __shfl_sync(0xffffffffu, a, l);
                int ccl = __shfl_sync(0xffffffffu, cc, l);
                bool mine = ((taken >> lane) & 1) && (a == aa || cc == ccl);
                unsigned conf = __ballot_sync(0xffffffffu, mine);
                if (!conf) { taken |= 1u << l; m++; }
            }
            if ((taken >> lane) & 1) { ua[a] = 1; ub[cc] = 1; partner[a] = cc; }
            __syncwarp();
        }
    }
    __syncthreads();

    // inclusive scan of kept-b indicator
    if (tid < 256) scan[tid] = ub[tid] ? 0 : 1;
    __syncthreads();
    for (int off = 1; off < 256; off <<= 1) {
        int v = 0;
        if (tid < 256) { v = scan[tid]; if (tid >= off) v += scan[tid - off]; }
        __syncthreads();
        if (tid < 256) scan[tid] = v;
        __syncthreads();
    }

    if (tid < 256) {
        int i = tid;
        int p = partner[i];
        g_srcA[b * TM_ + i] = 2 * i;
        g_srcB[b * TM_ + i] = (p >= 0) ? (2 * p + 1) : -1;
        g_dst0[b * TM_ + i] = 2 * i;
        g_dst1[b * TM_ + i] = (p >= 0) ? (2 * p + 1) : -1;
        if (!ub[i]) {
            int mm = TA_ + scan[i] - 1;
            g_srcA[b * TM_ + mm] = 2 * i + 1;
            g_srcB[b * TM_ + mm] = -1;
            g_dst0[b * TM_ + mm] = 2 * i + 1;
            g_dst1[b * TM_ + mm] = -1;
        }
    }
}

// ---------------- 5) merged sequence -> fp16 hi/lo ---------------------------
__global__ void kmerge(const float* __restrict__ x)
{
    int bm = blockIdx.x;
    int b = bm / TM_;
    int sA = g_srcA[bm], sB = g_srcB[bm];
    const float4* pa = (const float4*)(x + ((size_t)(b * T_ + sA)) * D_);
    const float4* pb = (sB >= 0) ? (const float4*)(x + ((size_t)(b * T_ + sB)) * D_) : nullptr;
    __half* mhi = g_mhi + (size_t)bm * D_;
    __half* mlo = g_mlo + (size_t)bm * D_;
    for (int i = threadIdx.x; i < D_ / 4; i += blockDim.x) {
        float4 a = pa[i];
        float v[4] = {a.x, a.y, a.z, a.w};
        if (pb) {
            float4 c = pb[i];
            v[0] = 0.5f * (v[0] + c.x); v[1] = 0.5f * (v[1] + c.y);
            v[2] = 0.5f * (v[2] + c.z); v[3] = 0.5f * (v[3] + c.w);
        }
        __half hh[4], ll[4];
#pragma unroll
        for (int q = 0; q < 4; q++) fp16_split(v[q], hh[q], ll[q]);
        __half2 t0, t1;
        t0.x = hh[0]; t0.y = hh[1]; t1.x = hh[2]; t1.y = hh[3];
        *(__half2*)(mhi + i * 4)     = t0;
        *(__half2*)(mhi + i * 4 + 2) = t1;
        t0.x = ll[0]; t0.y = ll[1]; t1.x = ll[2]; t1.y = ll[3];
        *(__half2*)(mlo + i * 4)     = t0;
        *(__half2*)(mlo + i * 4 + 2) = t1;
    }
}

// ---------------- 6) fused Q/K/V projection (z=0: 2-term; z=1,2: 1-term) -----
__global__ void __launch_bounds__(256) kqkv()
{
    int z = blockIdx.z;
    int m0 = blockIdx.y * 128, n0 = blockIdx.x * 128;
    int lane = threadIdx.x & 31, wid = threadIdx.x >> 5;
    int wrow = wid / 2, wcol = wid % 2;
    int g = lane >> 2, t4 = lane & 3;

    if (z == 0) {
        using G = MmaGemmH<128,128,4,2,true>;
        const __half* Bhi = g_whi + (size_t)n0 * D_;
        float acc[G::MT][G::NTT][4];
        G::run(g_mhi + (size_t)m0 * D_, g_mlo + (size_t)m0 * D_, D_, Bhi, D_, D_, acc);
#pragma unroll
        for (int i = 0; i < G::MT; i++)
#pragma unroll
            for (int rr = 0; rr < 2; rr++) {
                int m = m0 + wrow * 32 + i * 16 + g + rr * 8;
                int b = m / TM_, t = m % TM_;
#pragma unroll
                for (int j = 0; j < G::NTT; j++) {
                    int n = n0 + wcol * 64 + j * 8 + 2 * t4;
                    int h = n >> 6, d = n & 63;
                    size_t base = (((size_t)(b * H_ + h)) * TM_ + t) * HD_ + d;
                    __half h0, l0, h1, l1;
                    fp16_split(acc[i][j][rr * 2] * 0.125f, h0, l0);
                    fp16_split(acc[i][j][rr * 2 + 1] * 0.125f, h1, l1);
                    __half2 th, tl;
                    th.x = h0; th.y = h1; *(__half2*)(g_qhi + base) = th;
                    tl.x = l0; tl.y = l1; *(__half2*)(g_qlo + base) = tl;
                }
            }
    } else {
        using G = MmaGemmH<128,128,4,2,false>;
        const __half* Bhi = g_whi + (size_t)z * D_ * D_ + (size_t)n0 * D_;
        float acc[G::MT][G::NTT][4];
        G::run(g_mhi + (size_t)m0 * D_, nullptr, D_, Bhi, D_, D_, acc);
        __half* Dst = (z == 1) ? g_khi : g_vhi;
#pragma unroll
        for (int i = 0; i < G::MT; i++)
#pragma unroll
            for (int rr = 0; rr < 2; rr++) {
                int m = m0 + wrow * 32 + i * 16 + g + rr * 8;
                int b = m / TM_, t = m % TM_;
#pragma unroll
                for (int j = 0; j < G::NTT; j++) {
                    int n = n0 + wcol * 64 + j * 8 + 2 * t4;
                    int h = n >> 6, d = n & 63;
                    size_t base = (((size_t)(b * H_ + h)) * TM_ + t) * HD_ + d;
                    __half2 th;
                    th.x = __float2half_rn(acc[i][j][rr * 2]);
                    th.y = __float2half_rn(acc[i][j][rr * 2 + 1]);
                    *(__half2*)(Dst + base) = th;
                }
            }
    }
}

// ---------------- 7) fused attention (fp16; P hi-only in PV) -----------------
#define ATTN_SMEM 98304
__global__ void __launch_bounds__(256) kattn()
{
    extern __shared__ unsigned char smem_raw[];
    __half* sm = (__half*)smem_raw;
    float* smax0 = (float*)(smem_raw + 97280);
    float* smax1 = smax0 + 64;
    float* ssum0 = smax0 + 128;
    float* ssum1 = smax0 + 192;

    const int bh = blockIdx.y;
    const int m0 = blockIdx.x * 64;
    const int tid = threadIdx.x, lane = tid & 31, wid = tid >> 5;
    const int wrow = wid >> 1, wcol = wid & 1;
    const int g = lane >> 2, t4 = lane & 3;

    __half* sQhi = sm;
    __half* sQlo = sm + 4608;
    __half* sKhi = sm + 9216;

    {
        const __half* qh = g_qhi + ((size_t)bh * TM_ + m0) * HD_;
        const __half* ql = g_qlo + ((size_t)bh * TM_ + m0) * HD_;
        for (int idx = tid; idx < 64 * 8; idx += 256) {
            int r = idx >> 3, q = idx & 7;
            *(uint4*)(sQhi + r * 72 + q * 8) = *(const uint4*)(qh + r * HD_ + q * 8);
            *(uint4*)(sQlo + r * 72 + q * 8) = *(const uint4*)(ql + r * HD_ + q * 8);
        }
        const __half* kh = g_khi + (size_t)bh * TM_ * HD_;
        for (int idx = tid; idx < 384 * 8; idx += 256) {
            int r = idx >> 3, q = idx & 7;
            *(uint4*)(sKhi + r * 72 + q * 8) = *(const uint4*)(kh + r * HD_ + q * 8);
        }
    }
    __syncthreads();

    float acc[24][4];
#pragma unroll
    for (int j = 0; j < 24; j++)
#pragma unroll
        for (int e = 0; e < 4; e++) acc[j][e] = 0.f;

    const int arow  = wrow * 16 + (lane & 15);
    const int acolL = (lane >> 4) * 8;
    const int bg    = lane >> 3;
    const int brow0 = wcol * 192 + ((bg >> 1) << 3) + (lane & 7);
    const int bcolL = (bg & 1) << 3;

#pragma unroll
    for (int kk = 0; kk < 4; kk++) {
        uint4 ahi = ldm4(sQhi + arow * 72 + kk * 16 + acolL);
        uint4 alo = ldm4(sQlo + arow * 72 + kk * 16 + acolL);
#pragma unroll
        for (int jp = 0; jp < 12; jp++) {
            int off = (brow0 + jp * 16) * 72 + kk * 16 + bcolL;
            uint4 bhi = ldm4(sKhi + off);
            mma_h(acc[2*jp],   ahi, bhi.x, bhi.y);
            mma_h(acc[2*jp],   alo, bhi.x, bhi.y);
            mma_h(acc[2*jp+1], ahi, bhi.z, bhi.w);
            mma_h(acc[2*jp+1], alo, bhi.z, bhi.w);
        }
    }

    const int r0 = wrow * 16 + g, r1 = r0 + 8;
    float mx0 = -1e30f, mx1 = -1e30f;
#pragma unroll
    for (int j = 0; j < 24; j++) {
        mx0 = fmaxf(mx0, fmaxf(acc[j][0], acc[j][1]));
        mx1 = fmaxf(mx1, fmaxf(acc[j][2], acc[j][3]));
    }
    mx0 = fmaxf(mx0, __shfl_xor_sync(0xffffffffu, mx0, 1));
    mx0 = fmaxf(mx0, __shfl_xor_sync(0xffffffffu, mx0, 2));
    mx1 = fmaxf(mx1, __shfl_xor_sync(0xffffffffu, mx1, 1));
    mx1 = fmaxf(mx1, __shfl_xor_sync(0xffffffffu, mx1, 2));
    if (t4 == 0) {
        (wcol ? smax1 : smax0)[r0] = mx0;
        (wcol ? smax1 : smax0)[r1] = mx1;
    }
    __syncthreads();
    float M0 = fmaxf(smax0[r0], smax1[r0]);
    float M1 = fmaxf(smax0[r1], smax1[r1]);
    float s0 = 0.f, s1 = 0.f;
#pragma unroll
    for (int j = 0; j < 24; j++) {
        acc[j][0] = expf(acc[j][0] - M0); s0 += acc[j][0];
        acc[j][1] = expf(acc[j][1] - M0); s0 += acc[j][1];
        acc[j][2] = expf(acc[j][2] - M1); s1 += acc[j][2];
        acc[j][3] = expf(acc[j][3] - M1); s1 += acc[j][3];
    }
    s0 += __shfl_xor_sync(0xffffffffu, s0, 1); s0 += __shfl_xor_sync(0xffffffffu, s0, 2);
    s1 += __shfl_xor_sync(0xffffffffu, s1, 1); s1 += __shfl_xor_sync(0xffffffffu, s1, 2);
    if (t4 == 0) {
        (wcol ? ssum1 : ssum0)[r0] = s0;
        (wcol ? ssum1 : ssum0)[r1] = s1;
    }
    __syncthreads();

    {
        __half* sPhi = sm + 9216 + wcol * 12800;
#pragma unroll
        for (int j = 0; j < 24; j++) {
            int col = j * 8 + 2 * t4;
            __half2 th;
            th.x = __float2half_rn(acc[j][0]);
            th.y = __float2half_rn(acc[j][1]);
            *(__half2*)(sPhi + r0 * 200 + col) = th;
            th.x = __float2half_rn(acc[j][2]);
            th.y = __float2half_rn(acc[j][3]);
            *(__half2*)(sPhi + r1 * 200 + col) = th;
        }
    }
    __syncthreads();

    float acc2[4][4];
#pragma unroll
    for (int j = 0; j < 4; j++)
#pragma unroll
        for (int e = 0; e < 4; e++) acc2[j][e] = 0.f;

    __half* sVhi = sm + 34816;
    const int arow2 = wrow * 16 + (lane & 15);
    const int vrowL = ((bg & 1) << 3) + (lane & 7);
    const int vcolL = (bg >> 1) << 3;

    for (int c = 0; c < 2; c++) {
        if (c) __syncthreads();
        const __half* vh = g_vhi + ((size_t)bh * TM_ + c * 192) * HD_;
        for (int idx = tid; idx < 192 * 8; idx += 256) {
            int r = idx >> 3, q = idx & 7;
            *(uint4*)(sVhi + r * 72 + q * 8) = *(const uint4*)(vh + r * HD_ + q * 8);
        }
        __syncthreads();
        const __half* cPhi = sm + 9216 + c * 12800;
#pragma unroll
        for (int kk = 0; kk < 12; kk++) {
            uint4 phi = ldm4(cPhi + arow2 * 200 + kk * 16 + acolL);
#pragma unroll
            for (int jp = 0; jp < 2; jp++) {
                int off = (kk * 16 + vrowL) * 72 + wcol * 32 + jp * 16 + vcolL;
                uint4 vhi = ldm4t(sVhi + off);
                mma_h(acc2[2*jp],   phi, vhi.x, vhi.y);
                mma_h(acc2[2*jp+1], phi, vhi.z, vhi.w);
            }
        }
    }

    const int b = bh >> 4, hh = bh & 15;
    const float inv0 = 1.0f / (ssum0[r0] + ssum1[r0]);
    const float inv1 = 1.0f / (ssum0[r1] + ssum1[r1]);
#pragma unroll
    for (int j = 0; j < 4; j++) {
        int col = (wid & 1) * 32 + j * 8 + 2 * t4;
        int t  = m0 + r0;
        size_t o0 = ((size_t)(b * TM_ + t)) * D_ + hh * HD_ + col;
        size_t o1 = ((size_t)(b * TM_ + t + 8)) * D_ + hh * HD_ + col;
        __half h0, l0, h1, l1;
        __half2 th, tl;
        fp16_split(acc2[j][0] * inv0, h0, l0); fp16_split(acc2[j][1] * inv0, h1, l1);
        th.x = h0; th.y = h1; *(__half2*)(g_ahi + o0) = th;
        tl.x = l0; tl.y = l1; *(__half2*)(g_alo + o0) = tl;
        fp16_split(acc2[j][2] * inv1, h0, l0); fp16_split(acc2[j][3] * inv1, h1, l1);
        th.x = h0; th.y = h1; *(__half2*)(g_ahi + o1) = th;
        tl.x = l0; tl.y = l1; *(__half2*)(g_alo + o1) = tl;
    }
}

// ---------------- 8) output projection + fused unmerge scatter --------------
__global__ void __launch_bounds__(256) kout(float* __restrict__ out)
{
    using G = MmaGemmH<128,128,4,2,true>;
    int m0 = blockIdx.y * 128, n0 = blockIdx.x * 128;
    const __half* Bhi = g_whi + (size_t)3 * D_ * D_ + (size_t)n0 * D_;
    float acc[G::MT][G::NTT][4];
    G::run(g_ahi + (size_t)m0 * D_, g_alo + (size_t)m0 * D_, D_, Bhi, D_, D_, acc);

    int lane = threadIdx.x & 31, wid = threadIdx.x >> 5;
    int wrow = wid / 2, wcol = wid % 2;
    int g = lane >> 2, t4 = lane & 3;
#pragma unroll
    for (int i = 0; i < G::MT; i++) {
#pragma unroll
        for (int rr = 0; rr < 2; rr++) {
            int m = m0 + wrow * 32 + i * 16 + g + rr * 8;
            int b = m / TM_, mm = m % TM_;
            int d0 = g_dst0[b * TM_ + mm];
            int d1 = g_dst1[b * TM_ + mm];
#pragma unroll
            for (int j = 0; j < G::NTT; j++) {
                int n = n0 + wcol * 64 + j * 8 + 2 * t4;
                float2 v = make_float2(acc[i][j][rr * 2], acc[i][j][rr * 2 + 1]);
                *(float2*)&out[((size_t)(b * T_ + d0)) * D_ + n] = v;
                if (d1 >= 0) *(float2*)&out[((size_t)(b * T_ + d1)) * D_ + n] = v;
            }
        }
    }
}

// ---------------- launcher ----------------------------------------------------
extern "C" void kernel_launch(void* const* d_in, const int* in_sizes, int n_in,
                              void* d_out, int out_size)
{
    const float* x  = (const float*)d_in[0];
    const float* Wq = (const float*)d_in[1];
    const float* Wk = (const float*)d_in[2];
    const float* Wv = (const float*)d_in[3];
    const float* Wo = (const float*)d_in[4];
    float* out = (float*)d_out;

    const int smem_h2 = MmaGemmH<128,128,4,2,true>::SMEM;   // 110592
    const int smem_b  = MmaGemmB<64,64,2,4>::SMEM;          // 40960

    cudaFuncSetAttribute(kqkv,     cudaFuncAttributeMaxDynamicSharedMemorySize, smem_h2);
    cudaFuncSetAttribute(kout,     cudaFuncAttributeMaxDynamicSharedMemorySize, smem_h2);
    cudaFuncSetAttribute(ksim_mma, cudaFuncAttributeMaxDynamicSharedMemorySize, smem_b);
    cudaFuncSetAttribute(kattn,    cudaFuncAttributeMaxDynamicSharedMemorySize, ATTN_SMEM);

    kprepconv<<<8192, 256>>>(x, Wq, Wk, Wv, Wo);
    ksim_mma<<<dim3(4, 4, B_), 256, smem_b>>>();
    khistcut<<<dim3(8, B_), 256>>>();
    ksortgreedy<<<B_, 1024, SORT_SMEM>>>();
    kmerge<<<B_ * TM_, 256>>>(x);
    kqkv<<<dim3(8, 24, 3), 256, smem_h2>>>();
    kattn<<<dim3(6, B_ * H_), 256, ATTN_SMEM>>>();
    kout<<<dim3(8, 24), 256, smem_h2>>>(out);
}

// round 13
// speedup vs baseline: 1.2179x; 1.0068x over previous
#include <cuda_runtime.h>
#include <cuda_bf16.h>
#include <cuda_fp16.h>
#include <math.h>
#include <stdint.h>

#define B_   8
#define T_   512
#define D_   1024
#define H_   16
#define HD_  64
#define TA_  256
#define TB_  256
#define R_   128
#define TM_  384
#define NPAIR 65536
#define NCAP  2048

// ---------------- scratch (device globals) -----------------------------------
__device__ float              g_inv [B_*T_];
__device__ __align__(16) unsigned long long g_keys[B_*NPAIR];
__device__ unsigned long long g_cand[B_*NCAP];
__device__ int                g_hist[B_*4096];
__device__ int                g_done[B_];
__device__ int                g_cut [B_];
__device__ int                g_cnt [B_];
__device__ int                g_srcA[B_*TM_];
__device__ int                g_srcB[B_*TM_];
__device__ int                g_dst0[B_*TM_];
__device__ int                g_dst1[B_*TM_];
// fp16 operands (A side hi/lo, B side hi only)
__device__ __align__(16) __half g_mhi [B_*TM_*D_];
__device__ __align__(16) __half g_mlo [B_*TM_*D_];
__device__ __align__(16) __half g_whi [4*D_*D_];
__device__ __align__(16) __half g_qhi [B_*H_*TM_*HD_];
__device__ __align__(16) __half g_qlo [B_*H_*TM_*HD_];
__device__ __align__(16) __half g_khi [B_*H_*TM_*HD_];
__device__ __align__(16) __half g_vhi [B_*H_*TM_*HD_];
__device__ __align__(16) __half g_ahi [B_*TM_*D_];
__device__ __align__(16) __half g_alo [B_*TM_*D_];
// packed even/odd token sets for similarity mma (bf16 3-term, exact-order path)
__device__ __align__(16) __nv_bfloat16 g_xahi[B_*TA_*D_];
__device__ __align__(16) __nv_bfloat16 g_xalo[B_*TA_*D_];
__device__ __align__(16) __nv_bfloat16 g_xbhi[B_*TB_*D_];
__device__ __align__(16) __nv_bfloat16 g_xblo[B_*TB_*D_];

// ---------------- helpers -----------------------------------------------------
__device__ __forceinline__ void bf16_split(float v, __nv_bfloat16& h, __nv_bfloat16& l)
{
    h = __float2bfloat16(v);
    l = __float2bfloat16(v - __bfloat162float(h));
}

__device__ __forceinline__ void fp16_split(float v, __half& h, __half& l)
{
    h = __float2half_rn(v);
    l = __float2half_rn(v - __half2float(h));
}

__device__ __forceinline__ uint4 ldm4(const void* p)
{
    uint4 r; unsigned a = (unsigned)__cvta_generic_to_shared(p);
    asm volatile("ldmatrix.sync.aligned.m8n8.x4.shared.b16 {%0,%1,%2,%3}, [%4];"
        : "=r"(r.x), "=r"(r.y), "=r"(r.z), "=r"(r.w) : "r"(a));
    return r;
}

__device__ __forceinline__ uint4 ldm4t(const void* p)
{
    uint4 r; unsigned a = (unsigned)__cvta_generic_to_shared(p);
    asm volatile("ldmatrix.sync.aligned.m8n8.x4.trans.shared.b16 {%0,%1,%2,%3}, [%4];"
        : "=r"(r.x), "=r"(r.y), "=r"(r.z), "=r"(r.w) : "r"(a));
    return r;
}

__device__ __forceinline__ void mma_bf(float* c, uint4 a, unsigned b0, unsigned b1)
{
    asm volatile("mma.sync.aligned.m16n8k16.row.col.f32.bf16.bf16.f32 "
        "{%0,%1,%2,%3},{%4,%5,%6,%7},{%8,%9},{%0,%1,%2,%3};"
        : "+f"(c[0]), "+f"(c[1]), "+f"(c[2]), "+f"(c[3])
        : "r"(a.x), "r"(a.y), "r"(a.z), "r"(a.w), "r"(b0), "r"(b1));
}

__device__ __forceinline__ void mma_h(float* c, uint4 a, unsigned b0, unsigned b1)
{
    asm volatile("mma.sync.aligned.m16n8k16.row.col.f32.f16.f16.f32 "
        "{%0,%1,%2,%3},{%4,%5,%6,%7},{%8,%9},{%0,%1,%2,%3};"
        : "+f"(c[0]), "+f"(c[1]), "+f"(c[2]), "+f"(c[3])
        : "r"(a.x), "r"(a.y), "r"(a.z), "r"(a.w), "r"(b0), "r"(b1));
}

__device__ __forceinline__ void cpa16(void* dst, const void* src)
{
    unsigned d = (unsigned)__cvta_generic_to_shared(dst);
    asm volatile("cp.async.ca.shared.global [%0], [%1], 16;" :: "r"(d), "l"(src));
}
__device__ __forceinline__ void cp_commit() { asm volatile("cp.async.commit_group;"); }
__device__ __forceinline__ void cp_wait1()  { asm volatile("cp.async.wait_group 1;"); }
__device__ __forceinline__ void cp_wait0()  { asm volatile("cp.async.wait_group 0;"); }

// ====== fp16 GEMM, BK=64: C = (Ahi[+Alo]) · Bhi^T =============================
template<int BM, int BN, int WM, int WN, bool ALO>
struct MmaGemmH {
    static constexpr int MT  = BM / WM / 16;
    static constexpr int NTT = BN / WN / 8;
    static constexpr int BK  = 64;
    static constexpr int BKP = 72;
    static constexpr int AROWS = ALO ? 2 * BM : BM;
    static constexpr int STAGE = (AROWS + BN) * BKP;     // half elems per stage
    static constexpr int SMEM  = 2 * STAGE * 2;          // bytes

    __device__ static void prefetch(const __half* Ahi, const __half* Alo, int lda,
                                    const __half* Bhi, int ldb, int k0, __half* sbuf)
    {
        const int tid = threadIdx.x;
#pragma unroll
        for (int idx = tid; idx < BM * 8; idx += 256) {
            int m = idx >> 3, q = idx & 7;
            cpa16(sbuf + m * BKP + q * 8, Ahi + (size_t)m * lda + k0 + q * 8);
            if (ALO)
                cpa16(sbuf + BM * BKP + m * BKP + q * 8, Alo + (size_t)m * lda + k0 + q * 8);
        }
#pragma unroll
        for (int idx = tid; idx < BN * 8; idx += 256) {
            int n = idx >> 3, q = idx & 7;
            cpa16(sbuf + AROWS * BKP + n * BKP + q * 8, Bhi + (size_t)n * ldb + k0 + q * 8);
        }
    }

    __device__ static void run(const __half* Ahi, const __half* Alo, int lda,
                               const __half* Bhi, int ldb,
                               int K, float (&acc)[MT][NTT][4])
    {
        extern __shared__ unsigned char smem_raw[];
        __half* sm = (__half*)smem_raw;
        const int lane = threadIdx.x & 31;
        const int wid  = threadIdx.x >> 5;
        const int wrow = wid / WN, wcol = wid % WN;
#pragma unroll
        for (int i = 0; i < MT; i++)
#pragma unroll
            for (int j = 0; j < NTT; j++)
#pragma unroll
                for (int e = 0; e < 4; e++) acc[i][j][e] = 0.f;

        const int arow0 = wrow * (MT * 16) + (lane & 15);
        const int acolL = (lane >> 4) * 8;
        const int bg    = lane >> 3;
        const int brow0 = wcol * (NTT * 8) + ((bg >> 1) << 3) + (lane & 7);
        const int bcolL = (bg & 1) << 3;

        const int iters = K / BK;
        prefetch(Ahi, Alo, lda, Bhi, ldb, 0, sm);
        cp_commit();
        for (int it = 0; it < iters; it++) {
            if (it + 1 < iters) {
                prefetch(Ahi, Alo, lda, Bhi, ldb, (it + 1) * BK, sm + ((it + 1) & 1) * STAGE);
                cp_commit();
                cp_wait1();
            } else {
                cp_wait0();
            }
            __syncthreads();
            const __half* buf  = sm + (it & 1) * STAGE;
            const __half* sAhi = buf;
            const __half* sAlo = buf + BM * BKP;
            const __half* sBhi = buf + AROWS * BKP;
#pragma unroll
            for (int kk = 0; kk < 4; kk++) {
                uint4 ahi[MT], alo[MT];
#pragma unroll
                for (int i = 0; i < MT; i++) {
                    int off = (arow0 + i * 16) * BKP + kk * 16 + acolL;
                    ahi[i] = ldm4(sAhi + off);
                    if (ALO) alo[i] = ldm4(sAlo + off);
                }
#pragma unroll
                for (int jp = 0; jp < NTT / 2; jp++) {
                    int off = (brow0 + jp * 16) * BKP + kk * 16 + bcolL;
                    uint4 bhi = ldm4(sBhi + off);
#pragma unroll
                    for (int i = 0; i < MT; i++) {
                        mma_h(acc[i][2*jp],   ahi[i], bhi.x, bhi.y);
                        if (ALO) mma_h(acc[i][2*jp], alo[i], bhi.x, bhi.y);
                        mma_h(acc[i][2*jp+1], ahi[i], bhi.z, bhi.w);
                        if (ALO) mma_h(acc[i][2*jp+1], alo[i], bhi.z, bhi.w);
                    }
                }
            }
            __syncthreads();
        }
    }
};

// ====== bf16 3-term GEMM (similarity / exact-order path only) =================
template<int BM, int BN, int WM, int WN>
struct MmaGemmB {
    static constexpr int MT  = BM / WM / 16;
    static constexpr int NTT = BN / WN / 8;
    static constexpr int BK  = 32;
    static constexpr int BKP = 40;
    static constexpr int STAGE = (BM + BN) * 2 * BKP;
    static constexpr int SMEM  = 2 * STAGE * 2;

    __device__ static void prefetch(const __nv_bfloat16* Ahi, const __nv_bfloat16* Alo, int lda,
                                    const __nv_bfloat16* Bhi, const __nv_bfloat16* Blo, int ldb,
                                    int k0, __nv_bfloat16* sbuf)
    {
        const int tid = threadIdx.x;
#pragma unroll
        for (int idx = tid; idx < BM * 4; idx += 256) {
            int m = idx >> 2, q = idx & 3;
            cpa16(sbuf + m * BKP + q * 8,            Ahi + (size_t)m * lda + k0 + q * 8);
            cpa16(sbuf + BM * BKP + m * BKP + q * 8, Alo + (size_t)m * lda + k0 + q * 8);
        }
#pragma unroll
        for (int idx = tid; idx < BN * 4; idx += 256) {
            int n = idx >> 2, q = idx & 3;
            cpa16(sbuf + 2*BM*BKP + n * BKP + q * 8,          Bhi + (size_t)n * ldb + k0 + q * 8);
            cpa16(sbuf + 2*BM*BKP + BN*BKP + n * BKP + q * 8, Blo + (size_t)n * ldb + k0 + q * 8);
        }
    }

    __device__ static void run(const __nv_bfloat16* Ahi, const __nv_bfloat16* Alo, int lda,
                               const __nv_bfloat16* Bhi, const __nv_bfloat16* Blo, int ldb,
                               int K, float (&acc)[MT][NTT][4])
    {
        extern __shared__ unsigned char smem_raw[];
        __nv_bfloat16* sm = (__nv_bfloat16*)smem_raw;
        const int lane = threadIdx.x & 31;
        const int wid  = threadIdx.x >> 5;
        const int wrow = wid / WN, wcol = wid % WN;
#pragma unroll
        for (int i = 0; i < MT; i++)
#pragma unroll
            for (int j = 0; j < NTT; j++)
#pragma unroll
                for (int e = 0; e < 4; e++) acc[i][j][e] = 0.f;

        const int arow0 = wrow * (MT * 16) + (lane & 15);
        const int acolL = (lane >> 4) * 8;
        const int bg    = lane >> 3;
        const int brow0 = wcol * (NTT * 8) + ((bg >> 1) << 3) + (lane & 7);
        const int bcolL = (bg & 1) << 3;

        const int iters = K / BK;
        prefetch(Ahi, Alo, lda, Bhi, Blo, ldb, 0, sm);
        cp_commit();
        for (int it = 0; it < iters; it++) {
            if (it + 1 < iters) {
                prefetch(Ahi, Alo, lda, Bhi, Blo, ldb, (it + 1) * BK, sm + ((it + 1) & 1) * STAGE);
                cp_commit();
                cp_wait1();
            } else {
                cp_wait0();
            }
            __syncthreads();
            const __nv_bfloat16* buf  = sm + (it & 1) * STAGE;
            const __nv_bfloat16* sAhi = buf;
            const __nv_bfloat16* sAlo = buf + BM * BKP;
            const __nv_bfloat16* sBhi = buf + 2 * BM * BKP;
            const __nv_bfloat16* sBlo = buf + 2 * BM * BKP + BN * BKP;
#pragma unroll
            for (int kk = 0; kk < 2; kk++) {
                uint4 ahi[MT], alo[MT];
#pragma unroll
                for (int i = 0; i < MT; i++) {
                    int off = (arow0 + i * 16) * BKP + kk * 16 + acolL;
                    ahi[i] = ldm4(sAhi + off);
                    alo[i] = ldm4(sAlo + off);
                }
#pragma unroll
                for (int jp = 0; jp < NTT / 2; jp++) {
                    int off = (brow0 + jp * 16) * BKP + kk * 16 + bcolL;
                    uint4 bhi = ldm4(sBhi + off);
                    uint4 blo = ldm4(sBlo + off);
#pragma unroll
                    for (int i = 0; i < MT; i++) {
                        mma_bf(acc[i][2*jp],   ahi[i], bhi.x, bhi.y);
                        mma_bf(acc[i][2*jp],   ahi[i], blo.x, blo.y);
                        mma_bf(acc[i][2*jp],   alo[i], bhi.x, bhi.y);
                        mma_bf(acc[i][2*jp+1], ahi[i], bhi.z, bhi.w);
                        mma_bf(acc[i][2*jp+1], ahi[i], blo.z, blo.w);
                        mma_bf(acc[i][2*jp+1], alo[i], bhi.z, bhi.w);
                    }
                }
            }
            __syncthreads();
        }
    }
};

// ---------------- 1) fused prep + weight conversion --------------------------
__global__ void kprepconv(const float* __restrict__ x,
                          const float* __restrict__ Wq, const float* __restrict__ Wk,
                          const float* __restrict__ Wv, const float* __restrict__ Wo)
{
    if (blockIdx.x < 4096) {
        int row = blockIdx.x;
        int b = row >> 9, t = row & 511;
        const float4* src = (const float4*)(x + (size_t)row * D_);
        int r2 = (b << 8) + (t >> 1);
        __nv_bfloat16* dh = ((t & 1) ? g_xbhi : g_xahi) + (size_t)r2 * D_;
        __nv_bfloat16* dl = ((t & 1) ? g_xblo : g_xalo) + (size_t)r2 * D_;
        int i = threadIdx.x;
        float4 v = src[i];
        float vv[4] = {v.x, v.y, v.z, v.w};
        __nv_bfloat16 hh[4], ll[4];
#pragma unroll
        for (int q = 0; q < 4; q++) bf16_split(vv[q], hh[q], ll[q]);
        __nv_bfloat162 t0, t1;
        t0.x = hh[0]; t0.y = hh[1]; t1.x = hh[2]; t1.y = hh[3];
        *(__nv_bfloat162*)(dh + i * 4)     = t0;
        *(__nv_bfloat162*)(dh + i * 4 + 2) = t1;
        t0.x = ll[0]; t0.y = ll[1]; t1.x = ll[2]; t1.y = ll[3];
        *(__nv_bfloat162*)(dl + i * 4)     = t0;
        *(__nv_bfloat162*)(dl + i * 4 + 2) = t1;

        float s = vv[0]*vv[0] + vv[1]*vv[1] + vv[2]*vv[2] + vv[3]*vv[3];
        __shared__ float red[8];
        for (int o = 16; o > 0; o >>= 1) s += __shfl_down_sync(0xffffffffu, s, o);
        if ((threadIdx.x & 31) == 0) red[threadIdx.x >> 5] = s;
        __syncthreads();
        if (threadIdx.x < 32) {
            float w = (threadIdx.x < 8) ? red[threadIdx.x] : 0.f;
            for (int o = 4; o > 0; o >>= 1) w += __shfl_down_sync(0xffffffffu, w, o);
            if (threadIdx.x == 0) g_inv[row] = 1.0f / fmaxf(sqrtf(w), 1e-12f);
        }
        if (row < 128) g_hist[row * 256 + threadIdx.x] = 0;
        if (row == 0 && threadIdx.x < B_) { g_done[threadIdx.x] = 0; g_cnt[threadIdx.x] = 0; }
    } else {
        int idx = blockIdx.x - 4096;
        int mat = idx >> 10, blk = idx & 1023;
        const float* W = (mat == 0) ? Wq : (mat == 1) ? Wk : (mat == 2) ? Wv : Wo;
        size_t base = (size_t)mat * D_ * D_;
        int i = blk * 256 + threadIdx.x;
        float4 v = *(const float4*)(W + (size_t)i * 4);
        __half2 t0, t1;
        t0.x = __float2half_rn(v.x); t0.y = __float2half_rn(v.y);
        t1.x = __float2half_rn(v.z); t1.y = __float2half_rn(v.w);
        *(__half2*)(g_whi + base + (size_t)i * 4)     = t0;
        *(__half2*)(g_whi + base + (size_t)i * 4 + 2) = t1;
    }
}

// ---------------- 2) similarity via bf16 3-term mma (64x64 tiles) ------------
__global__ void __launch_bounds__(256) ksim_mma()
{
    using G = MmaGemmB<64,64,2,4>;
    int b = blockIdx.z;
    int a0 = blockIdx.y * 64, c0 = blockIdx.x * 64;
    float acc[G::MT][G::NTT][4];
    G::run(g_xahi + ((size_t)(b * TA_ + a0)) * D_, g_xalo + ((size_t)(b * TA_ + a0)) * D_, D_,
           g_xbhi + ((size_t)(b * TB_ + c0)) * D_, g_xblo + ((size_t)(b * TB_ + c0)) * D_, D_,
           D_, acc);

    int lane = threadIdx.x & 31, wid = threadIdx.x >> 5;
    int wrow = wid / 4, wcol = wid % 4;
    int g = lane >> 2, t4 = lane & 3;
#pragma unroll
    for (int i = 0; i < G::MT; i++)
#pragma unroll
        for (int j = 0; j < G::NTT; j++)
#pragma unroll
            for (int e = 0; e < 4; e++) {
                int a = a0 + wrow * 32 + i * 16 + g + ((e >> 1) << 3);
                int c = c0 + wcol * 16 + j * 8 + 2 * t4 + (e & 1);
                float v = acc[i][j][e] * g_inv[b * T_ + 2 * a] * g_inv[b * T_ + 2 * c + 1];
                unsigned u = __float_as_uint(v);
                unsigned ord = u ^ ((u & 0x80000000u) ? 0xFFFFFFFFu : 0x80000000u);
                unsigned flat = (unsigned)(a * TB_ + c);
                g_keys[(size_t)b * NPAIR + flat] =
                    ((unsigned long long)ord << 32) | (unsigned)(~flat);
            }
}

// ---------------- 3) histogram + last-block threshold ------------------------
__global__ void khistcut()
{
    __shared__ int h[4096];
    __shared__ int strip[256];
    __shared__ int suffix[257];
    __shared__ int isLast;
    int chunk = blockIdx.x, b = blockIdx.y, tid = threadIdx.x;
    for (int i = tid; i < 4096; i += 256) h[i] = 0;
    __syncthreads();
    const uint4* kv = (const uint4*)(g_keys + (size_t)b * NPAIR + chunk * 8192);
#pragma unroll 4
    for (int i = tid; i < 4096; i += 256) {
        uint4 v = kv[i];
        atomicAdd(&h[v.y >> 20], 1);
        atomicAdd(&h[v.w >> 20], 1);
    }
    __syncthreads();
    for (int i = tid; i < 4096; i += 256) {
        int v = h[i];
        if (v) atomicAdd(&g_hist[b * 4096 + i], v);
    }
    __threadfence();
    if (tid == 0) isLast = (atomicAdd(&g_done[b], 1) == 7);
    __syncthreads();
    if (!isLast) return;

    for (int i = tid; i < 4096; i += 256) h[i] = g_hist[b * 4096 + i];
    __syncthreads();
    int s = 0;
#pragma unroll
    for (int k = 0; k < 16; k++) s += h[tid * 16 + k];
    strip[tid] = s;
    __syncthreads();
    if (tid == 0) {
        int acc = 0;
        suffix[256] = 0;
        for (int i = 255; i >= 0; i--) { acc += strip[i]; suffix[i] = acc; }
    }
    __syncthreads();
    if (suffix[tid] >= 1024 && suffix[tid + 1] < 1024) {
        int c = suffix[tid + 1];
        int cut = tid * 16;
        for (int bkt = tid * 16 + 15; bkt >= tid * 16; bkt--) {
            c += h[bkt];
            if (c >= 1024) { cut = bkt; break; }
        }
        g_cut[b] = cut;
    }
}

// ---------------- 4) wide-grid compaction ------------------------------------
__global__ void kcompact()
{
    int b = blockIdx.y;
    int base = blockIdx.x * 2048 + threadIdx.x;
    int cut = g_cut[b];
    const unsigned long long* keys = g_keys + (size_t)b * NPAIR;
#pragma unroll
    for (int r = 0; r < 8; r++) {
        int i = base + r * 256;
        unsigned long long k = keys[i];
        if ((int)(k >> 52) >= cut) {
            int pos = atomicAdd(&g_cnt[b], 1);
            if (pos < NCAP) g_cand[b * NCAP + pos] = k;
        }
    }
}

// ---------------- 5) sort + warp-parallel exact greedy -----------------------
__device__ __forceinline__ void bitonic_sort_desc(unsigned long long* sk, int N, int tid, int nt)
{
    for (int k = 2; k <= N; k <<= 1) {
        for (int j = k >> 1; j > 0; j >>= 1) {
            for (int i = tid; i < N; i += nt) {
                int ixj = i ^ j;
                if (ixj > i) {
                    bool dir = ((i & k) == 0);
                    unsigned long long x0 = sk[i], x1 = sk[ixj];
                    if (dir ? (x0 < x1) : (x0 > x1)) { sk[i] = x1; sk[ixj] = x0; }
                }
            }
            __syncthreads();
        }
    }
}

#define SORT_SMEM (NCAP*8 + 512 + 256*4 + 256*4)
__global__ void ksortgreedy()
{
    extern __shared__ unsigned char smem_raw[];
    unsigned long long* sk = (unsigned long long*)smem_raw;          // NCAP keys
    unsigned char* ua = smem_raw + NCAP * 8;                         // 256
    unsigned char* ub = ua + 256;                                    // 256
    int* partner = (int*)(ub + 256);                                 // 256 ints
    int* scan    = partner + 256;                                    // 256 ints
    int b = blockIdx.x, tid = threadIdx.x;
    if (tid < 256) { ua[tid] = 0; ub[tid] = 0; partner[tid] = -1; }
    int c = g_cnt[b]; if (c > NCAP) c = NCAP;
    for (int i = tid; i < NCAP; i += 1024)
        sk[i] = (i < c) ? g_cand[b * NCAP + i] : 0ull;
    __syncthreads();
    bitonic_sort_desc(sk, NCAP, tid, 1024);

    // warp 0: chunked greedy, identical order to the serial scan
    if (tid < 32) {
        int lane = tid;
        int m = 0;
        for (int base = 0; base < NCAP && m < R_; base += 32) {
            int idx = base + lane;
            unsigned long long k = sk[idx];
            unsigned flat = ~(unsigned)k;
            int a  = (int)((flat >> 8) & 255u);
            int cc = (int)(flat & 255u);
            bool avail = (idx < c) && !ua[a] && !ub[cc];
            unsigned availm = __ballot_sync(0xffffffffu, avail);
            unsigned taken = 0;
            for (int l = 0; l < 32; l++) {
                if (m >= R_) break;
                if (!((availm >> l) & 1)) continue;
                int aa  = __shfl_sync(0xffffffffu, a, l);
                int ccl = __shfl_sync(0xffffffffu, cc, l);
                bool mine = ((taken >> lane) & 1) && (a == aa || cc == ccl);
                unsigned conf = __ballot_sync(0xffffffffu, mine);
                if (!conf) { taken |= 1u << l; m++; }
            }
            if ((taken >> lane) & 1) { ua[a] = 1; ub[cc] = 1; partner[a] = cc; }
            __syncwarp();
        }
    }
    __syncthreads();

    // inclusive scan of kept-b indicator
    if (tid < 256) scan[tid] = ub[tid] ? 0 : 1;
    __syncthreads();
    for (int off = 1; off < 256; off <<= 1) {
        int v = 0;
        if (tid < 256) { v = scan[tid]; if (tid >= off) v += scan[tid - off]; }
        __syncthreads();
        if (tid < 256) scan[tid] = v;
        __syncthreads();
    }

    if (tid < 256) {
        int i = tid;
        int p = partner[i];
        g_srcA[b * TM_ + i] = 2 * i;
        g_srcB[b * TM_ + i] = (p >= 0) ? (2 * p + 1) : -1;
        g_dst0[b * TM_ + i] = 2 * i;
        g_dst1[b * TM_ + i] = (p >= 0) ? (2 * p + 1) : -1;
        if (!ub[i]) {
            int mm = TA_ + scan[i] - 1;
            g_srcA[b * TM_ + mm] = 2 * i + 1;
            g_srcB[b * TM_ + mm] = -1;
            g_dst0[b * TM_ + mm] = 2 * i + 1;
            g_dst1[b * TM_ + mm] = -1;
        }
    }
}

// ---------------- 6) merged sequence -> fp16 hi/lo ---------------------------
__global__ void kmerge(const float* __restrict__ x)
{
    int bm = blockIdx.x;
    int b = bm / TM_;
    int sA = g_srcA[bm], sB = g_srcB[bm];
    const float4* pa = (const float4*)(x + ((size_t)(b * T_ + sA)) * D_);
    const float4* pb = (sB >= 0) ? (const float4*)(x + ((size_t)(b * T_ + sB)) * D_) : nullptr;
    __half* mhi = g_mhi + (size_t)bm * D_;
    __half* mlo = g_mlo + (size_t)bm * D_;
    for (int i = threadIdx.x; i < D_ / 4; i += blockDim.x) {
        float4 a = pa[i];
        float v[4] = {a.x, a.y, a.z, a.w};
        if (pb) {
            float4 c = pb[i];
            v[0] = 0.5f * (v[0] + c.x); v[1] = 0.5f * (v[1] + c.y);
            v[2] = 0.5f * (v[2] + c.z); v[3] = 0.5f * (v[3] + c.w);
        }
        __half hh[4], ll[4];
#pragma unroll
        for (int q = 0; q < 4; q++) fp16_split(v[q], hh[q], ll[q]);
        __half2 t0, t1;
        t0.x = hh[0]; t0.y = hh[1]; t1.x = hh[2]; t1.y = hh[3];
        *(__half2*)(mhi + i * 4)     = t0;
        *(__half2*)(mhi + i * 4 + 2) = t1;
        t0.x = ll[0]; t0.y = ll[1]; t1.x = ll[2]; t1.y = ll[3];
        *(__half2*)(mlo + i * 4)     = t0;
        *(__half2*)(mlo + i * 4 + 2) = t1;
    }
}

// ---------------- 7) fused Q/K/V projection (z=0: 2-term; z=1,2: 1-term) -----
__global__ void __launch_bounds__(256) kqkv()
{
    int z = blockIdx.z;
    int m0 = blockIdx.y * 128, n0 = blockIdx.x * 128;
    int lane = threadIdx.x & 31, wid = threadIdx.x >> 5;
    int wrow = wid / 2, wcol = wid % 2;
    int g = lane >> 2, t4 = lane & 3;

    if (z == 0) {
        using G = MmaGemmH<128,128,4,2,true>;
        const __half* Bhi = g_whi + (size_t)n0 * D_;
        float acc[G::MT][G::NTT][4];
        G::run(g_mhi + (size_t)m0 * D_, g_mlo + (size_t)m0 * D_, D_, Bhi, D_, D_, acc);
#pragma unroll
        for (int i = 0; i < G::MT; i++)
#pragma unroll
            for (int rr = 0; rr < 2; rr++) {
                int m = m0 + wrow * 32 + i * 16 + g + rr * 8;
                int b = m / TM_, t = m % TM_;
#pragma unroll
                for (int j = 0; j < G::NTT; j++) {
                    int n = n0 + wcol * 64 + j * 8 + 2 * t4;
                    int h = n >> 6, d = n & 63;
                    size_t base = (((size_t)(b * H_ + h)) * TM_ + t) * HD_ + d;
                    __half h0, l0, h1, l1;
                    fp16_split(acc[i][j][rr * 2] * 0.125f, h0, l0);
                    fp16_split(acc[i][j][rr * 2 + 1] * 0.125f, h1, l1);
                    __half2 th, tl;
                    th.x = h0; th.y = h1; *(__half2*)(g_qhi + base) = th;
                    tl.x = l0; tl.y = l1; *(__half2*)(g_qlo + base) = tl;
                }
            }
    } else {
        using G = MmaGemmH<128,128,4,2,false>;
        const __half* Bhi = g_whi + (size_t)z * D_ * D_ + (size_t)n0 * D_;
        float acc[G::MT][G::NTT][4];
        G::run(g_mhi + (size_t)m0 * D_, nullptr, D_, Bhi, D_, D_, acc);
        __half* Dst = (z == 1) ? g_khi : g_vhi;
#pragma unroll
        for (int i = 0; i < G::MT; i++)
#pragma unroll
            for (int rr = 0; rr < 2; rr++) {
                int m = m0 + wrow * 32 + i * 16 + g + rr * 8;
                int b = m / TM_, t = m % TM_;
#pragma unroll
                for (int j = 0; j < G::NTT; j++) {
                    int n = n0 + wcol * 64 + j * 8 + 2 * t4;
                    int h = n >> 6, d = n & 63;
                    size_t base = (((size_t)(b * H_ + h)) * TM_ + t) * HD_ + d;
                    __half2 th;
                    th.x = __float2half_rn(acc[i][j][rr * 2]);
                    th.y = __float2half_rn(acc[i][j][rr * 2 + 1]);
                    *(__half2*)(Dst + base) = th;
                }
            }
    }
}

// ---------------- 8) fused attention (fp16; P hi-only in PV) -----------------
#define ATTN_SMEM 98304
__global__ void __launch_bounds__(256) kattn()
{
    extern __shared__ unsigned char smem_raw[];
    __half* sm = (__half*)smem_raw;
    float* smax0 = (float*)(smem_raw + 97280);
    float* smax1 = smax0 + 64;
    float* ssum0 = smax0 + 128;
    float* ssum1 = smax0 + 192;

    const int bh = blockIdx.y;
    const int m0 = blockIdx.x * 64;
    const int tid = threadIdx.x, lane = tid & 31, wid = tid >> 5;
    const int wrow = wid >> 1, wcol = wid & 1;
    const int g = lane >> 2, t4 = lane & 3;

    __half* sQhi = sm;
    __half* sQlo = sm + 4608;
    __half* sKhi = sm + 9216;

    {
        const __half* qh = g_qhi + ((size_t)bh * TM_ + m0) * HD_;
        const __half* ql = g_qlo + ((size_t)bh * TM_ + m0) * HD_;
        for (int idx = tid; idx < 64 * 8; idx += 256) {
            int r = idx >> 3, q = idx & 7;
            *(uint4*)(sQhi + r * 72 + q * 8) = *(const uint4*)(qh + r * HD_ + q * 8);
            *(uint4*)(sQlo + r * 72 + q * 8) = *(const uint4*)(ql + r * HD_ + q * 8);
        }
        const __half* kh = g_khi + (size_t)bh * TM_ * HD_;
        for (int idx = tid; idx < 384 * 8; idx += 256) {
            int r = idx >> 3, q = idx & 7;
            *(uint4*)(sKhi + r * 72 + q * 8) = *(const uint4*)(kh + r * HD_ + q * 8);
        }
    }
    __syncthreads();

    float acc[24][4];
#pragma unroll
    for (int j = 0; j < 24; j++)
#pragma unroll
        for (int e = 0; e < 4; e++) acc[j][e] = 0.f;

    const int arow  = wrow * 16 + (lane & 15);
    const int acolL = (lane >> 4) * 8;
    const int bg    = lane >> 3;
    const int brow0 = wcol * 192 + ((bg >> 1) << 3) + (lane & 7);
    const int bcolL = (bg & 1) << 3;

#pragma unroll
    for (int kk = 0; kk < 4; kk++) {
        uint4 ahi = ldm4(sQhi + arow * 72 + kk * 16 + acolL);
        uint4 alo = ldm4(sQlo + arow * 72 + kk * 16 + acolL);
#pragma unroll
        for (int jp = 0; jp < 12; jp++) {
            int off = (brow0 + jp * 16) * 72 + kk * 16 + bcolL;
            uint4 bhi = ldm4(sKhi + off);
            mma_h(acc[2*jp],   ahi, bhi.x, bhi.y);
            mma_h(acc[2*jp],   alo, bhi.x, bhi.y);
            mma_h(acc[2*jp+1], ahi, bhi.z, bhi.w);
            mma_h(acc[2*jp+1], alo, bhi.z, bhi.w);
        }
    }

    const int r0 = wrow * 16 + g, r1 = r0 + 8;
    float mx0 = -1e30f, mx1 = -1e30f;
#pragma unroll
    for (int j = 0; j < 24; j++) {
        mx0 = fmaxf(mx0, fmaxf(acc[j][0], acc[j][1]));
        mx1 = fmaxf(mx1, fmaxf(acc[j][2], acc[j][3]));
    }
    mx0 = fmaxf(mx0, __shfl_xor_sync(0xffffffffu, mx0, 1));
    mx0 = fmaxf(mx0, __shfl_xor_sync(0xffffffffu, mx0, 2));
    mx1 = fmaxf(mx1, __shfl_xor_sync(0xffffffffu, mx1, 1));
    mx1 = fmaxf(mx1, __shfl_xor_sync(0xffffffffu, mx1, 2));
    if (t4 == 0) {
        (wcol ? smax1 : smax0)[r0] = mx0;
        (wcol ? smax1 : smax0)[r1] = mx1;
    }
    __syncthreads();
    float M0 = fmaxf(smax0[r0], smax1[r0]);
    float M1 = fmaxf(smax0[r1], smax1[r1]);
    float s0 = 0.f, s1 = 0.f;
#pragma unroll
    for (int j = 0; j < 24; j++) {
        acc[j][0] = expf(acc[j][0] - M0); s0 += acc[j][0];
        acc[j][1] = expf(acc[j][1] - M0); s0 += acc[j][1];
        acc[j][2] = expf(acc[j][2] - M1); s1 += acc[j][2];
        acc[j][3] = expf(acc[j][3] - M1); s1 += acc[j][3];
    }
    s0 += __shfl_xor_sync(0xffffffffu, s0, 1); s0 += __shfl_xor_sync(0xffffffffu, s0, 2);
    s1 += __shfl_xor_sync(0xffffffffu, s1, 1); s1 += __shfl_xor_sync(0xffffffffu, s1, 2);
    if (t4 == 0) {
        (wcol ? ssum1 : ssum0)[r0] = s0;
        (wcol ? ssum1 : ssum0)[r1] = s1;
    }
    __syncthreads();

    {
        __half* sPhi = sm + 9216 + wcol * 12800;
#pragma unroll
        for (int j = 0; j < 24; j++) {
            int col = j * 8 + 2 * t4;
            __half2 th;
            th.x = __float2half_rn(acc[j][0]);
            th.y = __float2half_rn(acc[j][1]);
            *(__half2*)(sPhi + r0 * 200 + col) = th;
            th.x = __float2half_rn(acc[j][2]);
            th.y = __float2half_rn(acc[j][3]);
            *(__half2*)(sPhi + r1 * 200 + col) = th;
        }
    }
    __syncthreads();

    float acc2[4][4];
#pragma unroll
    for (int j = 0; j < 4; j++)
#pragma unroll
        for (int e = 0; e < 4; e++) acc2[j][e] = 0.f;

    __half* sVhi = sm + 34816;
    const int arow2 = wrow * 16 + (lane & 15);
    const int vrowL = ((bg & 1) << 3) + (lane & 7);
    const int vcolL = (bg >> 1) << 3;

    for (int c = 0; c < 2; c++) {
        if (c) __syncthreads();
        const __half* vh = g_vhi + ((size_t)bh * TM_ + c * 192) * HD_;
        for (int idx = tid; idx < 192 * 8; idx += 256) {
            int r = idx >> 3, q = idx & 7;
            *(uint4*)(sVhi + r * 72 + q * 8) = *(const uint4*)(vh + r * HD_ + q * 8);
        }
        __syncthreads();
        const __half* cPhi = sm + 9216 + c * 12800;
#pragma unroll
        for (int kk = 0; kk < 12; kk++) {
            uint4 phi = ldm4(cPhi + arow2 * 200 + kk * 16 + acolL);
#pragma unroll
            for (int jp = 0; jp < 2; jp++) {
                int off = (kk * 16 + vrowL) * 72 + wcol * 32 + jp * 16 + vcolL;
                uint4 vhi = ldm4t(sVhi + off);
                mma_h(acc2[2*jp],   phi, vhi.x, vhi.y);
                mma_h(acc2[2*jp+1], phi, vhi.z, vhi.w);
            }
        }
    }

    const int b = bh >> 4, hh = bh & 15;
    const float inv0 = 1.0f / (ssum0[r0] + ssum1[r0]);
    const float inv1 = 1.0f / (ssum0[r1] + ssum1[r1]);
#pragma unroll
    for (int j = 0; j < 4; j++) {
        int col = (wid & 1) * 32 + j * 8 + 2 * t4;
        int t  = m0 + r0;
        size_t o0 = ((size_t)(b * TM_ + t)) * D_ + hh * HD_ + col;
        size_t o1 = ((size_t)(b * TM_ + t + 8)) * D_ + hh * HD_ + col;
        __half h0, l0, h1, l1;
        __half2 th, tl;
        fp16_split(acc2[j][0] * inv0, h0, l0); fp16_split(acc2[j][1] * inv0, h1, l1);
        th.x = h0; th.y = h1; *(__half2*)(g_ahi + o0) = th;
        tl.x = l0; tl.y = l1; *(__half2*)(g_alo + o0) = tl;
        fp16_split(acc2[j][2] * inv1, h0, l0); fp16_split(acc2[j][3] * inv1, h1, l1);
        th.x = h0; th.y = h1; *(__half2*)(g_ahi + o1) = th;
        tl.x = l0; tl.y = l1; *(__half2*)(g_alo + o1) = tl;
    }
}

// ---------------- 9) output projection + fused unmerge scatter --------------
__global__ void __launch_bounds__(256) kout(float* __restrict__ out)
{
    using G = MmaGemmH<128,128,4,2,true>;
    int m0 = blockIdx.y * 128, n0 = blockIdx.x * 128;
    const __half* Bhi = g_whi + (size_t)3 * D_ * D_ + (size_t)n0 * D_;
    float acc[G::MT][G::NTT][4];
    G::run(g_ahi + (size_t)m0 * D_, g_alo + (size_t)m0 * D_, D_, Bhi, D_, D_, acc);

    int lane = threadIdx.x & 31, wid = threadIdx.x >> 5;
    int wrow = wid / 2, wcol = wid % 2;
    int g = lane >> 2, t4 = lane & 3;
#pragma unroll
    for (int i = 0; i < G::MT; i++) {
#pragma unroll
        for (int rr = 0; rr < 2; rr++) {
            int m = m0 + wrow * 32 + i * 16 + g + rr * 8;
            int b = m / TM_, mm = m % TM_;
            int d0 = g_dst0[b * TM_ + mm];
            int d1 = g_dst1[b * TM_ + mm];
#pragma unroll
            for (int j = 0; j < G::NTT; j++) {
                int n = n0 + wcol * 64 + j * 8 + 2 * t4;
                float2 v = make_float2(acc[i][j][rr * 2], acc[i][j][rr * 2 + 1]);
                *(float2*)&out[((size_t)(b * T_ + d0)) * D_ + n] = v;
                if (d1 >= 0) *(float2*)&out[((size_t)(b * T_ + d1)) * D_ + n] = v;
            }
        }
    }
}

// ---------------- launcher ----------------------------------------------------
extern "C" void kernel_launch(void* const* d_in, const int* in_sizes, int n_in,
                              void* d_out, int out_size)
{
    const float* x  = (const float*)d_in[0];
    const float* Wq = (const float*)d_in[1];
    const float* Wk = (const float*)d_in[2];
    const float* Wv = (const float*)d_in[3];
    const float* Wo = (const float*)d_in[4];
    float* out = (float*)d_out;

    const int smem_h2 = MmaGemmH<128,128,4,2,true>::SMEM;   // 110592
    const int smem_b  = MmaGemmB<64,64,2,4>::SMEM;          // 40960

    cudaFuncSetAttribute(kqkv,     cudaFuncAttributeMaxDynamicSharedMemorySize, smem_h2);
    cudaFuncSetAttribute(kout,     cudaFuncAttributeMaxDynamicSharedMemorySize, smem_h2);
    cudaFuncSetAttribute(ksim_mma, cudaFuncAttributeMaxDynamicSharedMemorySize, smem_b);
    cudaFuncSetAttribute(kattn,    cudaFuncAttributeMaxDynamicSharedMemorySize, ATTN_SMEM);

    kprepconv<<<8192, 256>>>(x, Wq, Wk, Wv, Wo);
    ksim_mma<<<dim3(4, 4, B_), 256, smem_b>>>();
    khistcut<<<dim3(8, B_), 256>>>();
    kcompact<<<dim3(32, B_), 256>>>();
    ksortgreedy<<<B_, 1024, SORT_SMEM>>>();
    kmerge<<<B_ * TM_, 256>>>(x);
    kqkv<<<dim3(8, 24, 3), 256, smem_h2>>>();
    kattn<<<dim3(6, B_ * H_), 256, ATTN_SMEM>>>();
    kout<<<dim3(8, 24), 256, smem_h2>>>(out);
}